// round 4
// baseline (speedup 1.0000x reference)
#include <cuda_runtime.h>
#include <cmath>

#define NPIX 4096
#define BATCH 8
#define DIM 384
#define TRI 1152
#define NHEADS 8
#define HEADC 48
#define HID 1021
#define HID2 2042

// ---------------- scratch layout (floats), with region reuse ----------------
// O_BIG region (75497472 floats) lifecycle:
//   phase 1: qkv1 [0..37748736) , qkv [37748736..75497472)
//   phase 2: oatt [0..12582912)   (qkv1 dead after dwconv; qkv still live above)
//   phase 3: pbuf [0..66912256)   (qkv dead after av/pout)
//   phase 4: y1   [0..33456128)   (pbuf dead after dwconv+lin -> cat)
static const long O_XN   = 0L;                       // 12582912 (xn, later xn2)
static const long O_BIG  = O_XN  + 12582912L;        // 75497472
static const long O_XA   = O_BIG + 75497472L;        // 12582912
static const long O_CAT  = O_XA  + 12582912L;        // 66912256
static const long O_SPFN = O_CAT + 66912256L;        // 12288
static const long O_SPM  = O_SPFN + 12288L;          // 1572864
static const long O_ATTN = O_SPM  + 1572864L;        // 147456
static const long O_M    = O_ATTN + 147456L;         // 147456
static const long O_PART = O_M    + 147456L;         // 1179648
static const long O_END  = O_PART + 1179648L;        // 170635264 floats = ~683 MB

__device__ float g_s[170635264L];

// ---------------- LayerNorm over channel dim (per pixel) ----------------
__global__ void ln_kernel(const float* __restrict__ x, const float* __restrict__ w,
                          const float* __restrict__ b, float* __restrict__ y) {
    __shared__ float tile[DIM * 16];
    __shared__ float red[16][16], red2[16][16];
    __shared__ float s_mu[16], s_rs[16];
    int g = blockIdx.x;
    long base = (long)(g >> 8) * DIM * NPIX + (long)(g & 255) * 16;
    int tid = threadIdx.x;
    for (int i = tid; i < DIM * 16; i += 256) {
        int c = i >> 4, p = i & 15;
        tile[i] = x[base + (long)c * NPIX + p];
    }
    __syncthreads();
    {
        int p = tid & 15, chunk = tid >> 4;
        float s = 0.f, s2 = 0.f;
        for (int c = chunk * 24; c < chunk * 24 + 24; c++) {
            float v = tile[c * 16 + p];
            s += v; s2 += v * v;
        }
        red[chunk][p] = s; red2[chunk][p] = s2;
    }
    __syncthreads();
    if (tid < 16) {
        float su = 0.f, su2 = 0.f;
        for (int ch = 0; ch < 16; ch++) { su += red[ch][tid]; su2 += red2[ch][tid]; }
        float mu = su / DIM;
        float var = su2 / DIM - mu * mu;
        s_mu[tid] = mu;
        s_rs[tid] = rsqrtf(var + 1e-5f);
    }
    __syncthreads();
    for (int i = tid; i < DIM * 16; i += 256) {
        int c = i >> 4, p = i & 15;
        y[base + (long)c * NPIX + p] = (tile[i] - s_mu[p]) * s_rs[p] * w[c] + b[c];
    }
}

// ---------------- generic batched SGEMM: C = A[M,K] * B[K,4096] + bias (+res) ----
__global__ void __launch_bounds__(256) sgemm128(
    const float* __restrict__ A, const float* __restrict__ Bm,
    const float* __restrict__ bias, const float* __restrict__ res,
    float* __restrict__ C, int M, int K, long sB, long sC, long sR) {
    __shared__ float As[8][128];
    __shared__ float Bs[8][128];
    const float* Bb = Bm + (long)blockIdx.z * sB;
    float* Cb = C + (long)blockIdx.z * sC;
    const float* Rb = res ? res + (long)blockIdx.z * sR : nullptr;
    int row0 = blockIdx.y * 128, col0 = blockIdx.x * 128;
    int tid = threadIdx.x;
    int tm = tid >> 4, tn = tid & 15;
    float acc[8][8];
#pragma unroll
    for (int i = 0; i < 8; i++)
#pragma unroll
        for (int j = 0; j < 8; j++) acc[i][j] = 0.f;

    int a_m = tid >> 1, a_kb = (tid & 1) * 4;
    int b_kk = tid >> 5, b_n = (tid & 31) * 4;

    for (int k0 = 0; k0 < K; k0 += 8) {
        int gr = row0 + a_m;
#pragma unroll
        for (int j = 0; j < 4; j++) {
            int kk = a_kb + j;
            float v = 0.f;
            if (gr < M && (k0 + kk) < K) v = A[(long)gr * K + k0 + kk];
            As[kk][a_m] = v;
        }
        float4 bv = make_float4(0.f, 0.f, 0.f, 0.f);
        if (k0 + b_kk < K) bv = *(const float4*)&Bb[(long)(k0 + b_kk) * NPIX + col0 + b_n];
        *(float4*)&Bs[b_kk][b_n] = bv;
        __syncthreads();
#pragma unroll
        for (int kk = 0; kk < 8; kk++) {
            float4 a0 = *(const float4*)&As[kk][tm * 8];
            float4 a1 = *(const float4*)&As[kk][tm * 8 + 4];
            float4 b0 = *(const float4*)&Bs[kk][tn * 8];
            float4 b1 = *(const float4*)&Bs[kk][tn * 8 + 4];
            float av[8] = {a0.x, a0.y, a0.z, a0.w, a1.x, a1.y, a1.z, a1.w};
            float bw[8] = {b0.x, b0.y, b0.z, b0.w, b1.x, b1.y, b1.z, b1.w};
#pragma unroll
            for (int i = 0; i < 8; i++)
#pragma unroll
                for (int j = 0; j < 8; j++) acc[i][j] += av[i] * bw[j];
        }
        __syncthreads();
    }
#pragma unroll
    for (int i = 0; i < 8; i++) {
        int m = row0 + tm * 8 + i;
        if (m >= M) break;
        float bs = bias[m];
        long rowoff = (long)m * NPIX + col0 + tn * 8;
#pragma unroll
        for (int j = 0; j < 8; j++) {
            float v = acc[i][j] + bs;
            if (Rb) v += Rb[rowoff + j];
            Cb[rowoff + j] = v;
        }
    }
}

// ---------------- depthwise 3x3 conv, pad 1 ----------------
__global__ void dwconv(const float* __restrict__ x, const float* __restrict__ w,
                       const float* __restrict__ bias, float* __restrict__ y,
                       long sIn, long sOut) {
    int p = blockIdx.x * 256 + threadIdx.x;
    int c = blockIdx.y, b = blockIdx.z;
    int h = p >> 6, wc = p & 63;
    const float* xin = x + (long)b * sIn + (long)c * NPIX;
    float acc = bias[c];
    const float* wt = w + c * 9;
#pragma unroll
    for (int dh = -1; dh <= 1; dh++) {
        int hh = h + dh;
        if (hh < 0 || hh >= 64) continue;
#pragma unroll
        for (int dw = -1; dw <= 1; dw++) {
            int ww = wc + dw;
            if (ww < 0 || ww >= 64) continue;
            acc += xin[hh * 64 + ww] * wt[(dh + 1) * 3 + (dw + 1)];
        }
    }
    y[(long)b * sOut + (long)c * NPIX + p] = acc;
}

// ---------------- L2 normalize over W (rows of 64), warp per row ------------
__global__ void l2n_w(const float* __restrict__ src, float* __restrict__ dst,
                      long nrows, long rows_per_b, long sB) {
    long row = (long)blockIdx.x * 8 + (threadIdx.x >> 5);
    if (row >= nrows) return;
    int lane = threadIdx.x & 31;
    long b = row / rows_per_b;
    long off = b * sB + (row % rows_per_b) * 64;
    float v0 = src[off + lane], v1 = src[off + lane + 32];
    float s = v0 * v0 + v1 * v1;
#pragma unroll
    for (int o = 16; o; o >>= 1) s += __shfl_xor_sync(0xffffffffu, s, o);
    float inv = 1.f / fmaxf(sqrtf(s), 1e-12f);
    dst[off + lane] = v0 * inv;
    dst[off + lane + 32] = v1 * inv;
}

// ---------------- L2 normalize over 4096 (in place), block per row ----------
__global__ void l2n_n(float* __restrict__ x, long sB) {
    float* r = x + (long)blockIdx.y * sB + (long)blockIdx.x * NPIX;
    __shared__ float red[8];
    int tid = threadIdx.x;
    float s = 0.f;
    for (int i = tid; i < NPIX; i += 256) { float v = r[i]; s += v * v; }
#pragma unroll
    for (int o = 16; o; o >>= 1) s += __shfl_xor_sync(0xffffffffu, s, o);
    if ((tid & 31) == 0) red[tid >> 5] = s;
    __syncthreads();
    if (tid == 0) {
        float t = 0.f;
        for (int i = 0; i < 8; i++) t += red[i];
        red[0] = 1.f / fmaxf(sqrtf(t), 1e-12f);
    }
    __syncthreads();
    float inv = red[0];
    for (int i = tid; i < NPIX; i += 256) r[i] *= inv;
}

// ---------------- spm = conv3x3(spfn broadcast, proj_w) + proj_b -------------
__global__ void spm_conv(const float* __restrict__ spfn, const float* __restrict__ w,
                         const float* __restrict__ b, float* __restrict__ spm) {
    int p = blockIdx.x * 256 + threadIdx.x;
    int o = blockIdx.y;
    int h = p >> 6, wc = p & 63;
    float acc = b[o];
    for (int c = 0; c < 3; c++) {
#pragma unroll
        for (int dh = -1; dh <= 1; dh++) {
            int hh = h + dh;
            if (hh < 0 || hh >= 64) continue;
#pragma unroll
            for (int dw = -1; dw <= 1; dw++) {
                int ww = wc + dw;
                if (ww < 0 || ww >= 64) continue;
                acc += spfn[c * NPIX + hh * 64 + ww] * w[o * 27 + c * 9 + (dh + 1) * 3 + (dw + 1)];
            }
        }
    }
    spm[(long)o * NPIX + p] = acc;
}

// ---------------- q *= spm (broadcast over batch) ----------------
__global__ void mul_spm(float* __restrict__ q, const float* __restrict__ spm) {
    int p = blockIdx.x * 256 + threadIdx.x;
    int c = blockIdx.y, b = blockIdx.z;
    q[(long)b * TRI * NPIX + (long)c * NPIX + p] *= spm[(long)c * NPIX + p];
}

// ---------------- attn partial: qs @ kr^T over 512-pixel slice -------------
__global__ void attn_part(const float* __restrict__ qkv, float* __restrict__ part) {
    int s = blockIdx.x, bh = blockIdx.y;
    int b = bh >> 3, hd = bh & 7;
    const float* Q  = qkv + (long)b * TRI * NPIX + (long)(hd * HEADC) * NPIX;
    const float* Kp = qkv + (long)b * TRI * NPIX + (long)(DIM + hd * HEADC) * NPIX;
    __shared__ float Qs[48][65], Ks[48][65];
    int tid = threadIdx.x;
    int ti = tid >> 4, tj = tid & 15;
    float acc[3][3] = {};
    for (int p0 = s * 512; p0 < s * 512 + 512; p0 += 64) {
        for (int i = tid; i < 48 * 64; i += 256) {
            int r = i >> 6, c = i & 63;
            Qs[r][c] = Q[(long)r * NPIX + p0 + c];
            Ks[r][c] = Kp[(long)r * NPIX + p0 + c];
        }
        __syncthreads();
#pragma unroll 4
        for (int p = 0; p < 64; p++) {
            float qr[3], kk[3];
#pragma unroll
            for (int r = 0; r < 3; r++) { qr[r] = Qs[ti * 3 + r][p]; kk[r] = Ks[tj * 3 + r][p]; }
#pragma unroll
            for (int r = 0; r < 3; r++)
#pragma unroll
                for (int c = 0; c < 3; c++) acc[r][c] += qr[r] * kk[c];
        }
        __syncthreads();
    }
    float* P = part + ((long)s * 64 + bh) * 2304;
#pragma unroll
    for (int r = 0; r < 3; r++)
#pragma unroll
        for (int c = 0; c < 3; c++)
            P[(ti * 3 + r) * 48 + tj * 3 + c] = acc[r][c];
}

// ---------------- reduce partials + temperature ----------------
__global__ void attn_reduce(const float* __restrict__ part, const float* __restrict__ temp,
                            float* __restrict__ attn) {
    int idx = blockIdx.x * 256 + threadIdx.x;  // < 147456
    int bh = idx / 2304;
    int hd = bh & 7;
    float s = 0.f;
#pragma unroll
    for (int sl = 0; sl < 8; sl++) s += part[(long)sl * 147456 + idx];
    attn[idx] = s * temp[hd];
}

// ---------------- blend: relu + 4x topk masked softmax folded into one M ----
__global__ void blend_kernel(const float* __restrict__ attn, float* __restrict__ Mout,
                             const float* __restrict__ a1, const float* __restrict__ a2,
                             const float* __restrict__ a3, const float* __restrict__ a4,
                             const float* __restrict__ wmix) {
    int bh = blockIdx.x;
    int i = threadIdx.x;
    if (i >= 48) return;
    const float* row = attn + (long)bh * 2304 + i * 48;
    float arr[48], srt[48];
    for (int j = 0; j < 48; j++) { arr[j] = row[j]; srt[j] = arr[j]; }
    for (int a = 1; a < 48; a++) {
        float key = srt[a];
        int b2 = a - 1;
        while (b2 >= 0 && srt[b2] < key) { srt[b2 + 1] = srt[b2]; b2--; }
        srt[b2 + 1] = key;
    }
    float A[4] = {a1[0], a2[0], a3[0], a4[0]};
    float w0 = wmix[0], w1 = wmix[1];
    float mw = fmaxf(w0, w1);
    float e0 = expf(w0 - mw), e1 = expf(w1 - mw);
    float wsm0 = e0 / (e0 + e1), wsm1 = e1 / (e0 + e1);
    float csum = A[0] + A[1] + A[2] + A[3];
    float outr[48];
    for (int j = 0; j < 48; j++) outr[j] = wsm0 * csum * fmaxf(arr[j], 0.f);
    const int kks[4] = {24, 32, 36, 38};
    for (int t = 0; t < 4; t++) {
        float thr = srt[kks[t] - 1];
        float mv[48];
        float mx = -1e30f;
        for (int j = 0; j < 48; j++) {
            float m = (arr[j] >= thr) ? arr[j] : arr[j] * 1e-6f;
            mv[j] = m;
            mx = fmaxf(mx, m);
        }
        float Z = 0.f;
        for (int j = 0; j < 48; j++) { mv[j] = expf(mv[j] - mx); Z += mv[j]; }
        float sc = wsm1 * A[t] / Z;
        for (int j = 0; j < 48; j++) outr[j] += sc * mv[j];
    }
    float* o = Mout + (long)bh * 2304 + i * 48;
    for (int j = 0; j < 48; j++) o[j] = outr[j];
}

// ---------------- out = M(48x48) @ V(48x4096) ----------------
__global__ void av_kernel(const float* __restrict__ Mb, const float* __restrict__ qkv,
                          float* __restrict__ out) {
    int bh = blockIdx.y;
    int b = bh >> 3, hd = bh & 7;
    const float* V = qkv + (long)b * TRI * NPIX + (long)(2 * DIM + hd * HEADC) * NPIX;
    __shared__ float Ms[48][49];
    int tid = threadIdx.x;
    for (int i = tid; i < 2304; i += 128) Ms[i / 48][i % 48] = Mb[(long)bh * 2304 + i];
    __syncthreads();
    int p = blockIdx.x * 128 + tid;
    float vreg[48];
#pragma unroll
    for (int j = 0; j < 48; j++) vreg[j] = V[(long)j * NPIX + p];
    float* O = out + (long)b * DIM * NPIX + (long)(hd * HEADC) * NPIX;
#pragma unroll 4
    for (int i = 0; i < 48; i++) {
        float s = 0.f;
#pragma unroll
        for (int j = 0; j < 48; j++) s += Ms[i][j] * vreg[j];
        O[(long)i * NPIX + p] = s;
    }
}

// ---------------- f = gelu(y) * y (exact gelu), in place ----------------
__global__ void gelu_mul(float* __restrict__ y, long n) {
    long i = (long)blockIdx.x * 256 + threadIdx.x;
    if (i >= n) return;
    float v = y[i];
    float g = 0.5f * v * (1.f + erff(v * 0.70710678118654752f));
    y[i] = g * v;
}

// ================================================================
extern "C" void kernel_launch(void* const* d_in, const int* in_sizes, int n_in,
                              void* d_out, int out_size) {
    const float* x       = (const float*)d_in[0];
    const float* spf     = (const float*)d_in[1];
    const float* ln1_w   = (const float*)d_in[2];
    const float* ln1_b   = (const float*)d_in[3];
    const float* qkv_w   = (const float*)d_in[4];
    const float* qkv_b   = (const float*)d_in[5];
    const float* qkvdw_w = (const float*)d_in[6];
    const float* qkvdw_b = (const float*)d_in[7];
    const float* proj_w  = (const float*)d_in[8];
    const float* proj_b  = (const float*)d_in[9];
    const float* temp    = (const float*)d_in[10];
    const float* a1      = (const float*)d_in[11];
    const float* a2      = (const float*)d_in[12];
    const float* a3      = (const float*)d_in[13];
    const float* a4      = (const float*)d_in[14];
    const float* wmix    = (const float*)d_in[15];
    const float* pout_w  = (const float*)d_in[16];
    const float* pout_b  = (const float*)d_in[17];
    const float* ln2_w   = (const float*)d_in[18];
    const float* ln2_b   = (const float*)d_in[19];
    const float* pin_w   = (const float*)d_in[20];
    const float* pin_b   = (const float*)d_in[21];
    const float* dw_w    = (const float*)d_in[22];
    const float* dw_b    = (const float*)d_in[23];
    const float* lin_w   = (const float*)d_in[24];
    const float* lin_b   = (const float*)d_in[25];
    const float* adj_w   = (const float*)d_in[26];
    const float* adj_b   = (const float*)d_in[27];
    const float* fout_w  = (const float*)d_in[28];
    const float* fout_b  = (const float*)d_in[29];

    float* S = nullptr;
    cudaGetSymbolAddress((void**)&S, g_s);
    float* xn   = S + O_XN;                        // phase 1
    float* qkv1 = S + O_BIG;
    float* qkv  = S + O_BIG + 37748736L;
    float* spfn = S + O_SPFN;
    float* spm  = S + O_SPM;
    float* attn = S + O_ATTN;
    float* Mb   = S + O_M;
    float* part = S + O_PART;
    float* oatt = S + O_BIG;                       // reuses qkv1
    float* xa   = S + O_XA;
    float* xn2  = S + O_XN;                        // reuses xn
    float* pbuf = S + O_BIG;                       // reuses qkv1+qkv
    float* cat  = S + O_CAT;
    float* y1   = S + O_BIG;                       // reuses pbuf

    const long sDIM  = (long)DIM * NPIX;
    const long sTRI  = (long)TRI * NPIX;
    const long sHID  = (long)HID * NPIX;
    const long sHID2 = (long)HID2 * NPIX;

    // ---- attention ----
    ln_kernel<<<2048, 256>>>(x, ln1_w, ln1_b, xn);
    sgemm128<<<dim3(32, 9, 8), 256>>>(qkv_w, xn, qkv_b, nullptr, qkv1, TRI, DIM, sDIM, sTRI, 0);
    dwconv<<<dim3(16, TRI, 8), 256>>>(qkv1, qkvdw_w, qkvdw_b, qkv, sTRI, sTRI);
    l2n_w<<<24, 256>>>(spf, spfn, 192, 192, 0);                       // spf rows
    l2n_w<<<24576, 256>>>(qkv, qkv, 196608, 24576, sTRI);             // q rows (in place)
    spm_conv<<<dim3(16, 384), 256>>>(spfn, proj_w, proj_b, spm);
    mul_spm<<<dim3(16, 384, 8), 256>>>(qkv, spm);
    l2n_n<<<dim3(768, 8), 256>>>(qkv, sTRI);                          // qs + kr rows
    attn_part<<<dim3(8, 64), 256>>>(qkv, part);
    attn_reduce<<<576, 256>>>(part, temp, attn);
    blend_kernel<<<64, 64>>>(attn, Mb, a1, a2, a3, a4, wmix);
    av_kernel<<<dim3(32, 64), 128>>>(Mb, qkv, oatt);
    sgemm128<<<dim3(32, 3, 8), 256>>>(pout_w, oatt, pout_b, x, xa, DIM, DIM, sDIM, sDIM, sDIM);

    // ---- feed forward ----
    ln_kernel<<<2048, 256>>>(xa, ln2_w, ln2_b, xn2);
    sgemm128<<<dim3(32, 16, 8), 256>>>(pin_w, xn2, pin_b, nullptr, pbuf, HID2, DIM, sDIM, sHID2, 0);
    dwconv<<<dim3(16, HID, 8), 256>>>(pbuf, dw_w, dw_b, cat, sHID2, sHID2);
    sgemm128<<<dim3(32, 8, 8), 256>>>(lin_w, pbuf + (long)HID * NPIX, lin_b, nullptr,
                                      cat + (long)HID * NPIX, HID, HID, sHID2, sHID2, 0);
    sgemm128<<<dim3(32, 8, 8), 256>>>(adj_w, cat, adj_b, nullptr, y1, HID, HID2, sHID2, sHID, 0);
    gelu_mul<<<130688, 256>>>(y1, 33456128L);
    sgemm128<<<dim3(32, 3, 8), 256>>>(fout_w, y1, fout_b, xa, (float*)d_out, DIM, HID, sHID, sDIM, sDIM);
}

// round 9
// speedup vs baseline: 1.7956x; 1.7956x over previous
#include <cuda_runtime.h>
#include <cstdint>
#include <cmath>

#define NPIX 4096
#define BATCH 8
#define DIM 384
#define TRI 1152
#define NHEADS 8
#define HEADC 48
#define HID 1021
#define HID2 2042

// ---------------- scratch layout (floats), with region reuse ----------------
static const long O_XN   = 0L;                       // 12582912 (xn, later xn2)
static const long O_BIG  = O_XN  + 12582912L;        // 75497472
static const long O_XA   = O_BIG + 75497472L;        // 12582912
static const long O_CAT  = O_XA  + 12582912L;        // 66912256
static const long O_SPFN = O_CAT + 66912256L;        // 12288
static const long O_SPM  = O_SPFN + 12288L;          // 1572864
static const long O_ATTN = O_SPM  + 1572864L;        // 147456
static const long O_M    = O_ATTN + 147456L;         // 147456
static const long O_PART = O_M    + 147456L;         // 1179648
static const long O_END  = O_PART + 1179648L;        // 170635264 floats

__device__ float g_s[170635264L];

// ---------------- LayerNorm over channel dim (per pixel) ----------------
__global__ void ln_kernel(const float* __restrict__ x, const float* __restrict__ w,
                          const float* __restrict__ b, float* __restrict__ y) {
    __shared__ float tile[DIM * 16];
    __shared__ float red[16][16], red2[16][16];
    __shared__ float s_mu[16], s_rs[16];
    int g = blockIdx.x;
    long base = (long)(g >> 8) * DIM * NPIX + (long)(g & 255) * 16;
    int tid = threadIdx.x;
    for (int i = tid; i < DIM * 16; i += 256) {
        int c = i >> 4, p = i & 15;
        tile[i] = x[base + (long)c * NPIX + p];
    }
    __syncthreads();
    {
        int p = tid & 15, chunk = tid >> 4;
        float s = 0.f, s2 = 0.f;
        for (int c = chunk * 24; c < chunk * 24 + 24; c++) {
            float v = tile[c * 16 + p];
            s += v; s2 += v * v;
        }
        red[chunk][p] = s; red2[chunk][p] = s2;
    }
    __syncthreads();
    if (tid < 16) {
        float su = 0.f, su2 = 0.f;
        for (int ch = 0; ch < 16; ch++) { su += red[ch][tid]; su2 += red2[ch][tid]; }
        float mu = su / DIM;
        float var = su2 / DIM - mu * mu;
        s_mu[tid] = mu;
        s_rs[tid] = rsqrtf(var + 1e-5f);
    }
    __syncthreads();
    for (int i = tid; i < DIM * 16; i += 256) {
        int c = i >> 4, p = i & 15;
        y[base + (long)c * NPIX + p] = (tile[i] - s_mu[p]) * s_rs[p] * w[c] + b[c];
    }
}

// ---------------- TF32 tensor-core GEMM: C = A[M,K] * B[K,4096] + bias (+res) ----
// 128x128x16 block tile, 256 threads = 8 warps (4m x 2n), warp tile 32x64.
#define PITCH 136
// cvt.rna.tf32.f32 requires a .b32 destination register ("=r", not "=f").
__device__ __forceinline__ float tf32r(float x) {
    uint32_t y;
    asm("cvt.rna.tf32.f32 %0, %1;" : "=r"(y) : "f"(x));
    return __uint_as_float(y);
}
__device__ __forceinline__ void mma8(float* d, const uint32_t* a, uint32_t b0, uint32_t b1) {
    asm volatile(
        "mma.sync.aligned.m16n8k8.row.col.f32.tf32.tf32.f32 "
        "{%0,%1,%2,%3},{%4,%5,%6,%7},{%8,%9},{%0,%1,%2,%3};"
        : "+f"(d[0]), "+f"(d[1]), "+f"(d[2]), "+f"(d[3])
        : "r"(a[0]), "r"(a[1]), "r"(a[2]), "r"(a[3]), "r"(b0), "r"(b1));
}

__global__ void __launch_bounds__(256) tgemm(
    const float* __restrict__ A, const float* __restrict__ Bm,
    const float* __restrict__ bias, const float* __restrict__ res,
    float* __restrict__ C, int M, int K, long sB, long sC, long sR) {
    __shared__ float As[2][16][PITCH];
    __shared__ float Bs[2][16][PITCH];
    int tid = threadIdx.x;
    int warp = tid >> 5, lane = tid & 31;
    int wm = warp & 3, wn = warp >> 2;
    int t = lane & 3, g = lane >> 2;
    int row0 = blockIdx.y * 128, col0 = blockIdx.x * 128;
    const float* Bb = Bm + (long)blockIdx.z * sB;
    float* Cb = C + (long)blockIdx.z * sC;
    const float* Rb = res ? res + (long)blockIdx.z * sR : nullptr;

    float acc[2][8][4];
#pragma unroll
    for (int mi = 0; mi < 2; mi++)
#pragma unroll
        for (int ni = 0; ni < 8; ni++)
#pragma unroll
            for (int j = 0; j < 4; j++) acc[mi][ni][j] = 0.f;

    // staging indices
    int arow = tid & 127;           // A: thread loads row (row0+arow), k-chunk of 8
    int ak   = (tid >> 7) * 8;
    int bk   = tid >> 5;            // B: k rows bk and bk+8, 4 cols
    int bc   = (tid & 31) * 4;
    long agrow = (long)(row0 + arow) * K;
    bool arow_ok = (row0 + arow) < M;

    float ra[8];
    float4 rb0, rb1;

    int nk = (K + 15) / 16;
    // prologue: stage k0 = 0
    {
        int k0 = 0;
#pragma unroll
        for (int j = 0; j < 8; j++) {
            int kk = k0 + ak + j;
            ra[j] = (arow_ok && kk < K) ? A[agrow + kk] : 0.f;
        }
        rb0 = make_float4(0.f, 0.f, 0.f, 0.f);
        rb1 = rb0;
        if (k0 + bk < K)     rb0 = *(const float4*)&Bb[(long)(k0 + bk) * NPIX + col0 + bc];
        if (k0 + bk + 8 < K) rb1 = *(const float4*)&Bb[(long)(k0 + bk + 8) * NPIX + col0 + bc];
#pragma unroll
        for (int j = 0; j < 8; j++) As[0][ak + j][arow] = tf32r(ra[j]);
        Bs[0][bk][bc] = tf32r(rb0.x); Bs[0][bk][bc + 1] = tf32r(rb0.y);
        Bs[0][bk][bc + 2] = tf32r(rb0.z); Bs[0][bk][bc + 3] = tf32r(rb0.w);
        Bs[0][bk + 8][bc] = tf32r(rb1.x); Bs[0][bk + 8][bc + 1] = tf32r(rb1.y);
        Bs[0][bk + 8][bc + 2] = tf32r(rb1.z); Bs[0][bk + 8][bc + 3] = tf32r(rb1.w);
    }
    __syncthreads();

    for (int it = 0; it < nk; it++) {
        int cur = it & 1;
        // prefetch next tile into registers
        if (it + 1 < nk) {
            int k0 = (it + 1) * 16;
#pragma unroll
            for (int j = 0; j < 8; j++) {
                int kk = k0 + ak + j;
                ra[j] = (arow_ok && kk < K) ? A[agrow + kk] : 0.f;
            }
            rb0 = make_float4(0.f, 0.f, 0.f, 0.f);
            rb1 = rb0;
            if (k0 + bk < K)     rb0 = *(const float4*)&Bb[(long)(k0 + bk) * NPIX + col0 + bc];
            if (k0 + bk + 8 < K) rb1 = *(const float4*)&Bb[(long)(k0 + bk + 8) * NPIX + col0 + bc];
        }
        // compute on smem[cur]
#pragma unroll
        for (int kb = 0; kb < 16; kb += 8) {
            uint32_t a[2][4];
#pragma unroll
            for (int mi = 0; mi < 2; mi++) {
                int mr = wm * 32 + mi * 16 + g;
                a[mi][0] = __float_as_uint(As[cur][kb + t][mr]);
                a[mi][1] = __float_as_uint(As[cur][kb + t][mr + 8]);
                a[mi][2] = __float_as_uint(As[cur][kb + t + 4][mr]);
                a[mi][3] = __float_as_uint(As[cur][kb + t + 4][mr + 8]);
            }
#pragma unroll
            for (int ni = 0; ni < 8; ni++) {
                int nc = wn * 64 + ni * 8 + g;
                uint32_t b0 = __float_as_uint(Bs[cur][kb + t][nc]);
                uint32_t b1 = __float_as_uint(Bs[cur][kb + t + 4][nc]);
                mma8(acc[0][ni], a[0], b0, b1);
                mma8(acc[1][ni], a[1], b0, b1);
            }
        }
        // store prefetched tile into the other buffer
        if (it + 1 < nk) {
            int nxt = 1 - cur;
#pragma unroll
            for (int j = 0; j < 8; j++) As[nxt][ak + j][arow] = tf32r(ra[j]);
            Bs[nxt][bk][bc] = tf32r(rb0.x); Bs[nxt][bk][bc + 1] = tf32r(rb0.y);
            Bs[nxt][bk][bc + 2] = tf32r(rb0.z); Bs[nxt][bk][bc + 3] = tf32r(rb0.w);
            Bs[nxt][bk + 8][bc] = tf32r(rb1.x); Bs[nxt][bk + 8][bc + 1] = tf32r(rb1.y);
            Bs[nxt][bk + 8][bc + 2] = tf32r(rb1.z); Bs[nxt][bk + 8][bc + 3] = tf32r(rb1.w);
        }
        __syncthreads();
    }

    // epilogue: bias + optional residual, float2 stores
#pragma unroll
    for (int mi = 0; mi < 2; mi++) {
        int r0r = row0 + wm * 32 + mi * 16 + g;
        int r1r = r0r + 8;
        float bs0 = (r0r < M) ? bias[r0r] : 0.f;
        float bs1 = (r1r < M) ? bias[r1r] : 0.f;
#pragma unroll
        for (int ni = 0; ni < 8; ni++) {
            int c = col0 + wn * 64 + ni * 8 + 2 * t;
            if (r0r < M) {
                long off = (long)r0r * NPIX + c;
                float2 v = make_float2(acc[mi][ni][0] + bs0, acc[mi][ni][1] + bs0);
                if (Rb) { v.x += Rb[off]; v.y += Rb[off + 1]; }
                *(float2*)&Cb[off] = v;
            }
            if (r1r < M) {
                long off = (long)r1r * NPIX + c;
                float2 v = make_float2(acc[mi][ni][2] + bs1, acc[mi][ni][3] + bs1);
                if (Rb) { v.x += Rb[off]; v.y += Rb[off + 1]; }
                *(float2*)&Cb[off] = v;
            }
        }
    }
}

// ---------------- depthwise 3x3 conv, pad 1 ----------------
__global__ void dwconv(const float* __restrict__ x, const float* __restrict__ w,
                       const float* __restrict__ bias, float* __restrict__ y,
                       long sIn, long sOut) {
    int p = blockIdx.x * 256 + threadIdx.x;
    int c = blockIdx.y, b = blockIdx.z;
    int h = p >> 6, wc = p & 63;
    const float* xin = x + (long)b * sIn + (long)c * NPIX;
    float acc = bias[c];
    const float* wt = w + c * 9;
#pragma unroll
    for (int dh = -1; dh <= 1; dh++) {
        int hh = h + dh;
        if (hh < 0 || hh >= 64) continue;
#pragma unroll
        for (int dw = -1; dw <= 1; dw++) {
            int ww = wc + dw;
            if (ww < 0 || ww >= 64) continue;
            acc += xin[hh * 64 + ww] * wt[(dh + 1) * 3 + (dw + 1)];
        }
    }
    y[(long)b * sOut + (long)c * NPIX + p] = acc;
}

// ---------------- L2 normalize over W (rows of 64), warp per row ------------
__global__ void l2n_w(const float* __restrict__ src, float* __restrict__ dst,
                      long nrows, long rows_per_b, long sB) {
    long row = (long)blockIdx.x * 8 + (threadIdx.x >> 5);
    if (row >= nrows) return;
    int lane = threadIdx.x & 31;
    long b = row / rows_per_b;
    long off = b * sB + (row % rows_per_b) * 64;
    float v0 = src[off + lane], v1 = src[off + lane + 32];
    float s = v0 * v0 + v1 * v1;
#pragma unroll
    for (int o = 16; o; o >>= 1) s += __shfl_xor_sync(0xffffffffu, s, o);
    float inv = 1.f / fmaxf(sqrtf(s), 1e-12f);
    dst[off + lane] = v0 * inv;
    dst[off + lane + 32] = v1 * inv;
}

// ---------------- L2 normalize over 4096 (in place), block per row ----------
__global__ void l2n_n(float* __restrict__ x, long sB) {
    float* r = x + (long)blockIdx.y * sB + (long)blockIdx.x * NPIX;
    __shared__ float red[8];
    int tid = threadIdx.x;
    float s = 0.f;
    for (int i = tid; i < NPIX; i += 256) { float v = r[i]; s += v * v; }
#pragma unroll
    for (int o = 16; o; o >>= 1) s += __shfl_xor_sync(0xffffffffu, s, o);
    if ((tid & 31) == 0) red[tid >> 5] = s;
    __syncthreads();
    if (tid == 0) {
        float tsum = 0.f;
        for (int i = 0; i < 8; i++) tsum += red[i];
        red[0] = 1.f / fmaxf(sqrtf(tsum), 1e-12f);
    }
    __syncthreads();
    float inv = red[0];
    for (int i = tid; i < NPIX; i += 256) r[i] *= inv;
}

// ---------------- spm = conv3x3(spfn broadcast, proj_w) + proj_b -------------
__global__ void spm_conv(const float* __restrict__ spfn, const float* __restrict__ w,
                         const float* __restrict__ b, float* __restrict__ spm) {
    int p = blockIdx.x * 256 + threadIdx.x;
    int o = blockIdx.y;
    int h = p >> 6, wc = p & 63;
    float acc = b[o];
    for (int c = 0; c < 3; c++) {
#pragma unroll
        for (int dh = -1; dh <= 1; dh++) {
            int hh = h + dh;
            if (hh < 0 || hh >= 64) continue;
#pragma unroll
            for (int dw = -1; dw <= 1; dw++) {
                int ww = wc + dw;
                if (ww < 0 || ww >= 64) continue;
                acc += spfn[c * NPIX + hh * 64 + ww] * w[o * 27 + c * 9 + (dh + 1) * 3 + (dw + 1)];
            }
        }
    }
    spm[(long)o * NPIX + p] = acc;
}

// ---------------- q *= spm (broadcast over batch) ----------------
__global__ void mul_spm(float* __restrict__ q, const float* __restrict__ spm) {
    int p = blockIdx.x * 256 + threadIdx.x;
    int c = blockIdx.y, b = blockIdx.z;
    q[(long)b * TRI * NPIX + (long)c * NPIX + p] *= spm[(long)c * NPIX + p];
}

// ---------------- attn partial: qs @ kr^T over 512-pixel slice -------------
__global__ void attn_part(const float* __restrict__ qkv, float* __restrict__ part) {
    int s = blockIdx.x, bh = blockIdx.y;
    int b = bh >> 3, hd = bh & 7;
    const float* Q  = qkv + (long)b * TRI * NPIX + (long)(hd * HEADC) * NPIX;
    const float* Kp = qkv + (long)b * TRI * NPIX + (long)(DIM + hd * HEADC) * NPIX;
    __shared__ float Qs[48][65], Ks[48][65];
    int tid = threadIdx.x;
    int ti = tid >> 4, tj = tid & 15;
    float acc[3][3] = {};
    for (int p0 = s * 512; p0 < s * 512 + 512; p0 += 64) {
        for (int i = tid; i < 48 * 64; i += 256) {
            int r = i >> 6, c = i & 63;
            Qs[r][c] = Q[(long)r * NPIX + p0 + c];
            Ks[r][c] = Kp[(long)r * NPIX + p0 + c];
        }
        __syncthreads();
#pragma unroll 4
        for (int p = 0; p < 64; p++) {
            float qr[3], kk[3];
#pragma unroll
            for (int r = 0; r < 3; r++) { qr[r] = Qs[ti * 3 + r][p]; kk[r] = Ks[tj * 3 + r][p]; }
#pragma unroll
            for (int r = 0; r < 3; r++)
#pragma unroll
                for (int c = 0; c < 3; c++) acc[r][c] += qr[r] * kk[c];
        }
        __syncthreads();
    }
    float* P = part + ((long)s * 64 + bh) * 2304;
#pragma unroll
    for (int r = 0; r < 3; r++)
#pragma unroll
        for (int c = 0; c < 3; c++)
            P[(ti * 3 + r) * 48 + tj * 3 + c] = acc[r][c];
}

// ---------------- reduce partials + temperature ----------------
__global__ void attn_reduce(const float* __restrict__ part, const float* __restrict__ temp,
                            float* __restrict__ attn) {
    int idx = blockIdx.x * 256 + threadIdx.x;  // < 147456
    int bh = idx / 2304;
    int hd = bh & 7;
    float s = 0.f;
#pragma unroll
    for (int sl = 0; sl < 8; sl++) s += part[(long)sl * 147456 + idx];
    attn[idx] = s * temp[hd];
}

// ---------------- blend: relu + 4x topk masked softmax folded into one M ----
__global__ void blend_kernel(const float* __restrict__ attn, float* __restrict__ Mout,
                             const float* __restrict__ a1, const float* __restrict__ a2,
                             const float* __restrict__ a3, const float* __restrict__ a4,
                             const float* __restrict__ wmix) {
    int bh = blockIdx.x;
    int i = threadIdx.x;
    if (i >= 48) return;
    const float* row = attn + (long)bh * 2304 + i * 48;
    float arr[48], srt[48];
    for (int j = 0; j < 48; j++) { arr[j] = row[j]; srt[j] = arr[j]; }
    for (int a = 1; a < 48; a++) {
        float key = srt[a];
        int b2 = a - 1;
        while (b2 >= 0 && srt[b2] < key) { srt[b2 + 1] = srt[b2]; b2--; }
        srt[b2 + 1] = key;
    }
    float A[4] = {a1[0], a2[0], a3[0], a4[0]};
    float w0 = wmix[0], w1 = wmix[1];
    float mw = fmaxf(w0, w1);
    float e0 = expf(w0 - mw), e1 = expf(w1 - mw);
    float wsm0 = e0 / (e0 + e1), wsm1 = e1 / (e0 + e1);
    float csum = A[0] + A[1] + A[2] + A[3];
    float outr[48];
    for (int j = 0; j < 48; j++) outr[j] = wsm0 * csum * fmaxf(arr[j], 0.f);
    const int kks[4] = {24, 32, 36, 38};
    for (int tt = 0; tt < 4; tt++) {
        float thr = srt[kks[tt] - 1];
        float mv[48];
        float mx = -1e30f;
        for (int j = 0; j < 48; j++) {
            float m = (arr[j] >= thr) ? arr[j] : arr[j] * 1e-6f;
            mv[j] = m;
            mx = fmaxf(mx, m);
        }
        float Z = 0.f;
        for (int j = 0; j < 48; j++) { mv[j] = expf(mv[j] - mx); Z += mv[j]; }
        float sc = wsm1 * A[tt] / Z;
        for (int j = 0; j < 48; j++) outr[j] += sc * mv[j];
    }
    float* o = Mout + (long)bh * 2304 + i * 48;
    for (int j = 0; j < 48; j++) o[j] = outr[j];
}

// ---------------- out = M(48x48) @ V(48x4096) ----------------
__global__ void av_kernel(const float* __restrict__ Mb, const float* __restrict__ qkv,
                          float* __restrict__ out) {
    int bh = blockIdx.y;
    int b = bh >> 3, hd = bh & 7;
    const float* V = qkv + (long)b * TRI * NPIX + (long)(2 * DIM + hd * HEADC) * NPIX;
    __shared__ float Ms[48][49];
    int tid = threadIdx.x;
    for (int i = tid; i < 2304; i += 128) Ms[i / 48][i % 48] = Mb[(long)bh * 2304 + i];
    __syncthreads();
    int p = blockIdx.x * 128 + tid;
    float vreg[48];
#pragma unroll
    for (int j = 0; j < 48; j++) vreg[j] = V[(long)j * NPIX + p];
    float* O = out + (long)b * DIM * NPIX + (long)(hd * HEADC) * NPIX;
#pragma unroll 4
    for (int i = 0; i < 48; i++) {
        float s = 0.f;
#pragma unroll
        for (int j = 0; j < 48; j++) s += Ms[i][j] * vreg[j];
        O[(long)i * NPIX + p] = s;
    }
}

// ---------------- f = gelu(y) * y (exact gelu), in place ----------------
__global__ void gelu_mul(float* __restrict__ y, long n) {
    long i = (long)blockIdx.x * 256 + threadIdx.x;
    if (i >= n) return;
    float v = y[i];
    float g = 0.5f * v * (1.f + erff(v * 0.70710678118654752f));
    y[i] = g * v;
}

// ================================================================
extern "C" void kernel_launch(void* const* d_in, const int* in_sizes, int n_in,
                              void* d_out, int out_size) {
    const float* x       = (const float*)d_in[0];
    const float* spf     = (const float*)d_in[1];
    const float* ln1_w   = (const float*)d_in[2];
    const float* ln1_b   = (const float*)d_in[3];
    const float* qkv_w   = (const float*)d_in[4];
    const float* qkv_b   = (const float*)d_in[5];
    const float* qkvdw_w = (const float*)d_in[6];
    const float* qkvdw_b = (const float*)d_in[7];
    const float* proj_w  = (const float*)d_in[8];
    const float* proj_b  = (const float*)d_in[9];
    const float* temp    = (const float*)d_in[10];
    const float* a1      = (const float*)d_in[11];
    const float* a2      = (const float*)d_in[12];
    const float* a3      = (const float*)d_in[13];
    const float* a4      = (const float*)d_in[14];
    const float* wmix    = (const float*)d_in[15];
    const float* pout_w  = (const float*)d_in[16];
    const float* pout_b  = (const float*)d_in[17];
    const float* ln2_w   = (const float*)d_in[18];
    const float* ln2_b   = (const float*)d_in[19];
    const float* pin_w   = (const float*)d_in[20];
    const float* pin_b   = (const float*)d_in[21];
    const float* dw_w    = (const float*)d_in[22];
    const float* dw_b    = (const float*)d_in[23];
    const float* lin_w   = (const float*)d_in[24];
    const float* lin_b   = (const float*)d_in[25];
    const float* adj_w   = (const float*)d_in[26];
    const float* adj_b   = (const float*)d_in[27];
    const float* fout_w  = (const float*)d_in[28];
    const float* fout_b  = (const float*)d_in[29];

    float* S = nullptr;
    cudaGetSymbolAddress((void**)&S, g_s);
    float* xn   = S + O_XN;
    float* qkv1 = S + O_BIG;
    float* qkv  = S + O_BIG + 37748736L;
    float* spfn = S + O_SPFN;
    float* spm  = S + O_SPM;
    float* attn = S + O_ATTN;
    float* Mb   = S + O_M;
    float* part = S + O_PART;
    float* oatt = S + O_BIG;                       // reuses qkv1
    float* xa   = S + O_XA;
    float* xn2  = S + O_XN;                        // reuses xn
    float* pbuf = S + O_BIG;                       // reuses qkv1+qkv
    float* cat  = S + O_CAT;
    float* y1   = S + O_BIG;                       // reuses pbuf

    const long sDIM  = (long)DIM * NPIX;
    const long sTRI  = (long)TRI * NPIX;
    const long sHID  = (long)HID * NPIX;
    const long sHID2 = (long)HID2 * NPIX;

    // ---- attention ----
    ln_kernel<<<2048, 256>>>(x, ln1_w, ln1_b, xn);
    tgemm<<<dim3(32, 9, 8), 256>>>(qkv_w, xn, qkv_b, nullptr, qkv1, TRI, DIM, sDIM, sTRI, 0);
    dwconv<<<dim3(16, TRI, 8), 256>>>(qkv1, qkvdw_w, qkvdw_b, qkv, sTRI, sTRI);
    l2n_w<<<24, 256>>>(spf, spfn, 192, 192, 0);                       // spf rows
    l2n_w<<<24576, 256>>>(qkv, qkv, 196608, 24576, sTRI);             // q rows (in place)
    spm_conv<<<dim3(16, 384), 256>>>(spfn, proj_w, proj_b, spm);
    mul_spm<<<dim3(16, 384, 8), 256>>>(qkv, spm);
    l2n_n<<<dim3(768, 8), 256>>>(qkv, sTRI);                          // qs + kr rows
    attn_part<<<dim3(8, 64), 256>>>(qkv, part);
    attn_reduce<<<576, 256>>>(part, temp, attn);
    blend_kernel<<<64, 64>>>(attn, Mb, a1, a2, a3, a4, wmix);
    av_kernel<<<dim3(32, 64), 128>>>(Mb, qkv, oatt);
    tgemm<<<dim3(32, 3, 8), 256>>>(pout_w, oatt, pout_b, x, xa, DIM, DIM, sDIM, sDIM, sDIM);

    // ---- feed forward ----
    ln_kernel<<<2048, 256>>>(xa, ln2_w, ln2_b, xn2);
    tgemm<<<dim3(32, 16, 8), 256>>>(pin_w, xn2, pin_b, nullptr, pbuf, HID2, DIM, sDIM, sHID2, 0);
    dwconv<<<dim3(16, HID, 8), 256>>>(pbuf, dw_w, dw_b, cat, sHID2, sHID2);
    tgemm<<<dim3(32, 8, 8), 256>>>(lin_w, pbuf + (long)HID * NPIX, lin_b, nullptr,
                                   cat + (long)HID * NPIX, HID, HID, sHID2, sHID2, 0);
    tgemm<<<dim3(32, 8, 8), 256>>>(adj_w, cat, adj_b, nullptr, y1, HID, HID2, sHID2, sHID, 0);
    gelu_mul<<<130688, 256>>>(y1, 33456128L);
    tgemm<<<dim3(32, 3, 8), 256>>>(fout_w, y1, fout_b, xa, (float*)d_out, DIM, HID, sHID, sDIM, sDIM);
}

// round 12
// speedup vs baseline: 2.1142x; 1.1774x over previous
#include <cuda_runtime.h>
#include <cstdint>
#include <cmath>

#define NPIX 4096
#define BATCH 8
#define DIM 384
#define TRI 1152
#define NHEADS 8
#define HEADC 48
#define HID 1021
#define HID2 2042

// ---------------- scratch layout (floats), with region reuse ----------------
static const long O_XN   = 0L;                       // 12582912 (xn, later xn2)
static const long O_BIG  = O_XN  + 12582912L;        // 75497472
static const long O_XA   = O_BIG + 75497472L;        // 12582912
static const long O_CAT  = O_XA  + 12582912L;        // 66912256
static const long O_SPFN = O_CAT + 66912256L;        // 12288
static const long O_SPM  = O_SPFN + 12288L;          // 1572864
static const long O_ATTN = O_SPM  + 1572864L;        // 147456
static const long O_M    = O_ATTN + 147456L;         // 147456
static const long O_PART = O_M    + 147456L;         // 1179648
static const long O_END  = O_PART + 1179648L;        // 170635264 floats

__device__ float g_s[170635264L];

// ---------------- LayerNorm over channel dim (per pixel) ----------------
__global__ void ln_kernel(const float* __restrict__ x, const float* __restrict__ w,
                          const float* __restrict__ b, float* __restrict__ y) {
    __shared__ float tile[DIM * 16];
    __shared__ float red[16][16], red2[16][16];
    __shared__ float s_mu[16], s_rs[16];
    int g = blockIdx.x;
    long base = (long)(g >> 8) * DIM * NPIX + (long)(g & 255) * 16;
    int tid = threadIdx.x;
    for (int i = tid; i < DIM * 16; i += 256) {
        int c = i >> 4, p = i & 15;
        tile[i] = x[base + (long)c * NPIX + p];
    }
    __syncthreads();
    {
        int p = tid & 15, chunk = tid >> 4;
        float s = 0.f, s2 = 0.f;
        for (int c = chunk * 24; c < chunk * 24 + 24; c++) {
            float v = tile[c * 16 + p];
            s += v; s2 += v * v;
        }
        red[chunk][p] = s; red2[chunk][p] = s2;
    }
    __syncthreads();
    if (tid < 16) {
        float su = 0.f, su2 = 0.f;
        for (int ch = 0; ch < 16; ch++) { su += red[ch][tid]; su2 += red2[ch][tid]; }
        float mu = su / DIM;
        float var = su2 / DIM - mu * mu;
        s_mu[tid] = mu;
        s_rs[tid] = rsqrtf(var + 1e-5f);
    }
    __syncthreads();
    for (int i = tid; i < DIM * 16; i += 256) {
        int c = i >> 4, p = i & 15;
        y[base + (long)c * NPIX + p] = (tile[i] - s_mu[p]) * s_rs[p] * w[c] + b[c];
    }
}

// ---------------- BF16 tensor-core GEMM: C = A[M,K] * B[K,4096] + bias (+res) ----
// 128x128x32 block tile, 256 threads = 8 warps (4m x 2n), warp tile 32x64.
// Smem holds bf16x2 pairs packed along K: As32[k2][m] = (A[m][2k2], A[m][2k2+1]).
#define P32 136
// cvt.rn.bf16x2.f32 d, a, b  ->  d.hi = bf16(a), d.lo = bf16(b). Pass (hi, lo).
__device__ __forceinline__ uint32_t packbf(float lo, float hi) {
    uint32_t d;
    asm("cvt.rn.bf16x2.f32 %0, %1, %2;" : "=r"(d) : "f"(hi), "f"(lo));
    return d;
}
__device__ __forceinline__ void mma16(float* d, const uint32_t* a, uint32_t b0, uint32_t b1) {
    asm volatile(
        "mma.sync.aligned.m16n8k16.row.col.f32.bf16.bf16.f32 "
        "{%0,%1,%2,%3},{%4,%5,%6,%7},{%8,%9},{%0,%1,%2,%3};"
        : "+f"(d[0]), "+f"(d[1]), "+f"(d[2]), "+f"(d[3])
        : "r"(a[0]), "r"(a[1]), "r"(a[2]), "r"(a[3]), "r"(b0), "r"(b1));
}

__global__ void __launch_bounds__(256) bgemm(
    const float* __restrict__ A, const float* __restrict__ Bm,
    const float* __restrict__ bias, const float* __restrict__ res,
    float* __restrict__ C, int M, int K, long sB, long sC, long sR) {
    __shared__ uint32_t As32[2][16][P32];
    __shared__ uint32_t Bs32[2][16][P32];
    int tid = threadIdx.x;
    int warp = tid >> 5, lane = tid & 31;
    int wm = warp & 3, wn = warp >> 2;
    int t = lane & 3, g = lane >> 2;
    int row0 = blockIdx.y * 128, col0 = blockIdx.x * 128;
    const float* Bb = Bm + (long)blockIdx.z * sB;
    float* Cb = C + (long)blockIdx.z * sC;
    const float* Rb = res ? res + (long)blockIdx.z * sR : nullptr;

    float acc[2][8][4];
#pragma unroll
    for (int mi = 0; mi < 2; mi++)
#pragma unroll
        for (int ni = 0; ni < 8; ni++)
#pragma unroll
            for (int j = 0; j < 4; j++) acc[mi][ni][j] = 0.f;

    // A staging: 2 threads per row; each covers 16 consecutive k (8 pairs)
    int arow = tid & 127;
    int ka2  = (tid >> 7) * 8;          // k2 offset: 0 or 8
    long agrow = (long)(row0 + arow) * K;
    bool arow_ok = (row0 + arow) < M;
    // B staging: thread covers k-pair bk2 (2 rows), 8 cols
    int bk2 = tid >> 4;                  // 0..15
    int bc8 = (tid & 15) * 8;            // 0..120

    float ra[16];
    float4 rb[4];

    int nk = (K + 31) / 32;
    // ---- prologue: stage chunk 0 into buffer 0 ----
    {
        int k0 = 0;
#pragma unroll
        for (int j = 0; j < 16; j++) {
            int kk = k0 + ka2 * 2 + j;
            ra[j] = (arow_ok && kk < K) ? A[agrow + kk] : 0.f;
        }
        int kr0 = k0 + bk2 * 2, kr1 = kr0 + 1;
        rb[0] = rb[1] = rb[2] = rb[3] = make_float4(0.f, 0.f, 0.f, 0.f);
        if (kr0 < K) {
            rb[0] = *(const float4*)&Bb[(long)kr0 * NPIX + col0 + bc8];
            rb[1] = *(const float4*)&Bb[(long)kr0 * NPIX + col0 + bc8 + 4];
        }
        if (kr1 < K) {
            rb[2] = *(const float4*)&Bb[(long)kr1 * NPIX + col0 + bc8];
            rb[3] = *(const float4*)&Bb[(long)kr1 * NPIX + col0 + bc8 + 4];
        }
#pragma unroll
        for (int j = 0; j < 8; j++) As32[0][ka2 + j][arow] = packbf(ra[2 * j], ra[2 * j + 1]);
        Bs32[0][bk2][bc8 + 0] = packbf(rb[0].x, rb[2].x);
        Bs32[0][bk2][bc8 + 1] = packbf(rb[0].y, rb[2].y);
        Bs32[0][bk2][bc8 + 2] = packbf(rb[0].z, rb[2].z);
        Bs32[0][bk2][bc8 + 3] = packbf(rb[0].w, rb[2].w);
        Bs32[0][bk2][bc8 + 4] = packbf(rb[1].x, rb[3].x);
        Bs32[0][bk2][bc8 + 5] = packbf(rb[1].y, rb[3].y);
        Bs32[0][bk2][bc8 + 6] = packbf(rb[1].z, rb[3].z);
        Bs32[0][bk2][bc8 + 7] = packbf(rb[1].w, rb[3].w);
    }
    __syncthreads();

    for (int it = 0; it < nk; it++) {
        int cur = it & 1;
        // prefetch next chunk into registers
        if (it + 1 < nk) {
            int k0 = (it + 1) * 32;
#pragma unroll
            for (int j = 0; j < 16; j++) {
                int kk = k0 + ka2 * 2 + j;
                ra[j] = (arow_ok && kk < K) ? A[agrow + kk] : 0.f;
            }
            int kr0 = k0 + bk2 * 2, kr1 = kr0 + 1;
            rb[0] = rb[1] = rb[2] = rb[3] = make_float4(0.f, 0.f, 0.f, 0.f);
            if (kr0 < K) {
                rb[0] = *(const float4*)&Bb[(long)kr0 * NPIX + col0 + bc8];
                rb[1] = *(const float4*)&Bb[(long)kr0 * NPIX + col0 + bc8 + 4];
            }
            if (kr1 < K) {
                rb[2] = *(const float4*)&Bb[(long)kr1 * NPIX + col0 + bc8];
                rb[3] = *(const float4*)&Bb[(long)kr1 * NPIX + col0 + bc8 + 4];
            }
        }
        // compute on smem[cur]: two k16 sub-chunks
#pragma unroll
        for (int c = 0; c < 2; c++) {
            uint32_t a[2][4];
#pragma unroll
            for (int mi = 0; mi < 2; mi++) {
                int mr = wm * 32 + mi * 16 + g;
                a[mi][0] = As32[cur][c * 8 + t][mr];
                a[mi][1] = As32[cur][c * 8 + t][mr + 8];
                a[mi][2] = As32[cur][c * 8 + t + 4][mr];
                a[mi][3] = As32[cur][c * 8 + t + 4][mr + 8];
            }
#pragma unroll
            for (int ni = 0; ni < 8; ni++) {
                int nc = wn * 64 + ni * 8 + g;
                uint32_t b0 = Bs32[cur][c * 8 + t][nc];
                uint32_t b1 = Bs32[cur][c * 8 + t + 4][nc];
                mma16(acc[0][ni], a[0], b0, b1);
                mma16(acc[1][ni], a[1], b0, b1);
            }
        }
        // store prefetched chunk into other buffer
        if (it + 1 < nk) {
            int nxt = 1 - cur;
#pragma unroll
            for (int j = 0; j < 8; j++) As32[nxt][ka2 + j][arow] = packbf(ra[2 * j], ra[2 * j + 1]);
            Bs32[nxt][bk2][bc8 + 0] = packbf(rb[0].x, rb[2].x);
            Bs32[nxt][bk2][bc8 + 1] = packbf(rb[0].y, rb[2].y);
            Bs32[nxt][bk2][bc8 + 2] = packbf(rb[0].z, rb[2].z);
            Bs32[nxt][bk2][bc8 + 3] = packbf(rb[0].w, rb[2].w);
            Bs32[nxt][bk2][bc8 + 4] = packbf(rb[1].x, rb[3].x);
            Bs32[nxt][bk2][bc8 + 5] = packbf(rb[1].y, rb[3].y);
            Bs32[nxt][bk2][bc8 + 6] = packbf(rb[1].z, rb[3].z);
            Bs32[nxt][bk2][bc8 + 7] = packbf(rb[1].w, rb[3].w);
        }
        __syncthreads();
    }

    // epilogue: bias + optional residual, float2 stores
#pragma unroll
    for (int mi = 0; mi < 2; mi++) {
        int r0r = row0 + wm * 32 + mi * 16 + g;
        int r1r = r0r + 8;
        float bs0 = (r0r < M) ? bias[r0r] : 0.f;
        float bs1 = (r1r < M) ? bias[r1r] : 0.f;
#pragma unroll
        for (int ni = 0; ni < 8; ni++) {
            int c = col0 + wn * 64 + ni * 8 + 2 * t;
            if (r0r < M) {
                long off = (long)r0r * NPIX + c;
                float2 v = make_float2(acc[mi][ni][0] + bs0, acc[mi][ni][1] + bs0);
                if (Rb) { v.x += Rb[off]; v.y += Rb[off + 1]; }
                *(float2*)&Cb[off] = v;
            }
            if (r1r < M) {
                long off = (long)r1r * NPIX + c;
                float2 v = make_float2(acc[mi][ni][2] + bs1, acc[mi][ni][3] + bs1);
                if (Rb) { v.x += Rb[off]; v.y += Rb[off + 1]; }
                *(float2*)&Cb[off] = v;
            }
        }
    }
}

// ---------------- depthwise 3x3 conv, pad 1 ----------------
__global__ void dwconv(const float* __restrict__ x, const float* __restrict__ w,
                       const float* __restrict__ bias, float* __restrict__ y,
                       long sIn, long sOut) {
    int p = blockIdx.x * 256 + threadIdx.x;
    int c = blockIdx.y, b = blockIdx.z;
    int h = p >> 6, wc = p & 63;
    const float* xin = x + (long)b * sIn + (long)c * NPIX;
    float acc = bias[c];
    const float* wt = w + c * 9;
#pragma unroll
    for (int dh = -1; dh <= 1; dh++) {
        int hh = h + dh;
        if (hh < 0 || hh >= 64) continue;
#pragma unroll
        for (int dw = -1; dw <= 1; dw++) {
            int ww = wc + dw;
            if (ww < 0 || ww >= 64) continue;
            acc += xin[hh * 64 + ww] * wt[(dh + 1) * 3 + (dw + 1)];
        }
    }
    y[(long)b * sOut + (long)c * NPIX + p] = acc;
}

// ---------------- L2 normalize over W (rows of 64), warp per row ------------
__global__ void l2n_w(const float* __restrict__ src, float* __restrict__ dst,
                      long nrows, long rows_per_b, long sB) {
    long row = (long)blockIdx.x * 8 + (threadIdx.x >> 5);
    if (row >= nrows) return;
    int lane = threadIdx.x & 31;
    long b = row / rows_per_b;
    long off = b * sB + (row % rows_per_b) * 64;
    float v0 = src[off + lane], v1 = src[off + lane + 32];
    float s = v0 * v0 + v1 * v1;
#pragma unroll
    for (int o = 16; o; o >>= 1) s += __shfl_xor_sync(0xffffffffu, s, o);
    float inv = 1.f / fmaxf(sqrtf(s), 1e-12f);
    dst[off + lane] = v0 * inv;
    dst[off + lane + 32] = v1 * inv;
}

// ---------------- L2 normalize over 4096 (in place), block per row ----------
__global__ void l2n_n(float* __restrict__ x, long sB) {
    float* r = x + (long)blockIdx.y * sB + (long)blockIdx.x * NPIX;
    __shared__ float red[8];
    int tid = threadIdx.x;
    float s = 0.f;
    for (int i = tid; i < NPIX; i += 256) { float v = r[i]; s += v * v; }
#pragma unroll
    for (int o = 16; o; o >>= 1) s += __shfl_xor_sync(0xffffffffu, s, o);
    if ((tid & 31) == 0) red[tid >> 5] = s;
    __syncthreads();
    if (tid == 0) {
        float tsum = 0.f;
        for (int i = 0; i < 8; i++) tsum += red[i];
        red[0] = 1.f / fmaxf(sqrtf(tsum), 1e-12f);
    }
    __syncthreads();
    float inv = red[0];
    for (int i = tid; i < NPIX; i += 256) r[i] *= inv;
}

// ---------------- spm = conv3x3(spfn broadcast, proj_w) + proj_b -------------
__global__ void spm_conv(const float* __restrict__ spfn, const float* __restrict__ w,
                         const float* __restrict__ b, float* __restrict__ spm) {
    int p = blockIdx.x * 256 + threadIdx.x;
    int o = blockIdx.y;
    int h = p >> 6, wc = p & 63;
    float acc = b[o];
    for (int c = 0; c < 3; c++) {
#pragma unroll
        for (int dh = -1; dh <= 1; dh++) {
            int hh = h + dh;
            if (hh < 0 || hh >= 64) continue;
#pragma unroll
            for (int dw = -1; dw <= 1; dw++) {
                int ww = wc + dw;
                if (ww < 0 || ww >= 64) continue;
                acc += spfn[c * NPIX + hh * 64 + ww] * w[o * 27 + c * 9 + (dh + 1) * 3 + (dw + 1)];
            }
        }
    }
    spm[(long)o * NPIX + p] = acc;
}

// ---------------- q *= spm (broadcast over batch) ----------------
__global__ void mul_spm(float* __restrict__ q, const float* __restrict__ spm) {
    int p = blockIdx.x * 256 + threadIdx.x;
    int c = blockIdx.y, b = blockIdx.z;
    q[(long)b * TRI * NPIX + (long)c * NPIX + p] *= spm[(long)c * NPIX + p];
}

// ---------------- attn partial: qs @ kr^T over 512-pixel slice -------------
__global__ void attn_part(const float* __restrict__ qkv, float* __restrict__ part) {
    int s = blockIdx.x, bh = blockIdx.y;
    int b = bh >> 3, hd = bh & 7;
    const float* Q  = qkv + (long)b * TRI * NPIX + (long)(hd * HEADC) * NPIX;
    const float* Kp = qkv + (long)b * TRI * NPIX + (long)(DIM + hd * HEADC) * NPIX;
    __shared__ float Qs[48][65], Ks[48][65];
    int tid = threadIdx.x;
    int ti = tid >> 4, tj = tid & 15;
    float acc[3][3] = {};
    for (int p0 = s * 512; p0 < s * 512 + 512; p0 += 64) {
        for (int i = tid; i < 48 * 64; i += 256) {
            int r = i >> 6, c = i & 63;
            Qs[r][c] = Q[(long)r * NPIX + p0 + c];
            Ks[r][c] = Kp[(long)r * NPIX + p0 + c];
        }
        __syncthreads();
#pragma unroll 4
        for (int p = 0; p < 64; p++) {
            float qr[3], kk[3];
#pragma unroll
            for (int r = 0; r < 3; r++) { qr[r] = Qs[ti * 3 + r][p]; kk[r] = Ks[tj * 3 + r][p]; }
#pragma unroll
            for (int r = 0; r < 3; r++)
#pragma unroll
                for (int c = 0; c < 3; c++) acc[r][c] += qr[r] * kk[c];
        }
        __syncthreads();
    }
    float* P = part + ((long)s * 64 + bh) * 2304;
#pragma unroll
    for (int r = 0; r < 3; r++)
#pragma unroll
        for (int c = 0; c < 3; c++)
            P[(ti * 3 + r) * 48 + tj * 3 + c] = acc[r][c];
}

// ---------------- reduce partials + temperature ----------------
__global__ void attn_reduce(const float* __restrict__ part, const float* __restrict__ temp,
                            float* __restrict__ attn) {
    int idx = blockIdx.x * 256 + threadIdx.x;  // < 147456
    int bh = idx / 2304;
    int hd = bh & 7;
    float s = 0.f;
#pragma unroll
    for (int sl = 0; sl < 8; sl++) s += part[(long)sl * 147456 + idx];
    attn[idx] = s * temp[hd];
}

// ---------------- blend: relu + 4x topk masked softmax folded into one M ----
__global__ void blend_kernel(const float* __restrict__ attn, float* __restrict__ Mout,
                             const float* __restrict__ a1, const float* __restrict__ a2,
                             const float* __restrict__ a3, const float* __restrict__ a4,
                             const float* __restrict__ wmix) {
    int bh = blockIdx.x;
    int i = threadIdx.x;
    if (i >= 48) return;
    const float* row = attn + (long)bh * 2304 + i * 48;
    float arr[48], srt[48];
    for (int j = 0; j < 48; j++) { arr[j] = row[j]; srt[j] = arr[j]; }
    for (int a = 1; a < 48; a++) {
        float key = srt[a];
        int b2 = a - 1;
        while (b2 >= 0 && srt[b2] < key) { srt[b2 + 1] = srt[b2]; b2--; }
        srt[b2 + 1] = key;
    }
    float A[4] = {a1[0], a2[0], a3[0], a4[0]};
    float w0 = wmix[0], w1 = wmix[1];
    float mw = fmaxf(w0, w1);
    float e0 = expf(w0 - mw), e1 = expf(w1 - mw);
    float wsm0 = e0 / (e0 + e1), wsm1 = e1 / (e0 + e1);
    float csum = A[0] + A[1] + A[2] + A[3];
    float outr[48];
    for (int j = 0; j < 48; j++) outr[j] = wsm0 * csum * fmaxf(arr[j], 0.f);
    const int kks[4] = {24, 32, 36, 38};
    for (int tt = 0; tt < 4; tt++) {
        float thr = srt[kks[tt] - 1];
        float mv[48];
        float mx = -1e30f;
        for (int j = 0; j < 48; j++) {
            float m = (arr[j] >= thr) ? arr[j] : arr[j] * 1e-6f;
            mv[j] = m;
            mx = fmaxf(mx, m);
        }
        float Z = 0.f;
        for (int j = 0; j < 48; j++) { mv[j] = expf(mv[j] - mx); Z += mv[j]; }
        float sc = wsm1 * A[tt] / Z;
        for (int j = 0; j < 48; j++) outr[j] += sc * mv[j];
    }
    float* o = Mout + (long)bh * 2304 + i * 48;
    for (int j = 0; j < 48; j++) o[j] = outr[j];
}

// ---------------- out = M(48x48) @ V(48x4096) ----------------
__global__ void av_kernel(const float* __restrict__ Mb, const float* __restrict__ qkv,
                          float* __restrict__ out) {
    int bh = blockIdx.y;
    int b = bh >> 3, hd = bh & 7;
    const float* V = qkv + (long)b * TRI * NPIX + (long)(2 * DIM + hd * HEADC) * NPIX;
    __shared__ float Ms[48][49];
    int tid = threadIdx.x;
    for (int i = tid; i < 2304; i += 128) Ms[i / 48][i % 48] = Mb[(long)bh * 2304 + i];
    __syncthreads();
    int p = blockIdx.x * 128 + tid;
    float vreg[48];
#pragma unroll
    for (int j = 0; j < 48; j++) vreg[j] = V[(long)j * NPIX + p];
    float* O = out + (long)b * DIM * NPIX + (long)(hd * HEADC) * NPIX;
#pragma unroll 4
    for (int i = 0; i < 48; i++) {
        float s = 0.f;
#pragma unroll
        for (int j = 0; j < 48; j++) s += Ms[i][j] * vreg[j];
        O[(long)i * NPIX + p] = s;
    }
}

// ---------------- f = gelu(y) * y (exact gelu), in place ----------------
__global__ void gelu_mul(float* __restrict__ y, long n) {
    long i = (long)blockIdx.x * 256 + threadIdx.x;
    if (i >= n) return;
    float v = y[i];
    float g = 0.5f * v * (1.f + erff(v * 0.70710678118654752f));
    y[i] = g * v;
}

// ================================================================
extern "C" void kernel_launch(void* const* d_in, const int* in_sizes, int n_in,
                              void* d_out, int out_size) {
    const float* x       = (const float*)d_in[0];
    const float* spf     = (const float*)d_in[1];
    const float* ln1_w   = (const float*)d_in[2];
    const float* ln1_b   = (const float*)d_in[3];
    const float* qkv_w   = (const float*)d_in[4];
    const float* qkv_b   = (const float*)d_in[5];
    const float* qkvdw_w = (const float*)d_in[6];
    const float* qkvdw_b = (const float*)d_in[7];
    const float* proj_w  = (const float*)d_in[8];
    const float* proj_b  = (const float*)d_in[9];
    const float* temp    = (const float*)d_in[10];
    const float* a1      = (const float*)d_in[11];
    const float* a2      = (const float*)d_in[12];
    const float* a3      = (const float*)d_in[13];
    const float* a4      = (const float*)d_in[14];
    const float* wmix    = (const float*)d_in[15];
    const float* pout_w  = (const float*)d_in[16];
    const float* pout_b  = (const float*)d_in[17];
    const float* ln2_w   = (const float*)d_in[18];
    const float* ln2_b   = (const float*)d_in[19];
    const float* pin_w   = (const float*)d_in[20];
    const float* pin_b   = (const float*)d_in[21];
    const float* dw_w    = (const float*)d_in[22];
    const float* dw_b    = (const float*)d_in[23];
    const float* lin_w   = (const float*)d_in[24];
    const float* lin_b   = (const float*)d_in[25];
    const float* adj_w   = (const float*)d_in[26];
    const float* adj_b   = (const float*)d_in[27];
    const float* fout_w  = (const float*)d_in[28];
    const float* fout_b  = (const float*)d_in[29];

    float* S = nullptr;
    cudaGetSymbolAddress((void**)&S, g_s);
    float* xn   = S + O_XN;
    float* qkv1 = S + O_BIG;
    float* qkv  = S + O_BIG + 37748736L;
    float* spfn = S + O_SPFN;
    float* spm  = S + O_SPM;
    float* attn = S + O_ATTN;
    float* Mb   = S + O_M;
    float* part = S + O_PART;
    float* oatt = S + O_BIG;                       // reuses qkv1
    float* xa   = S + O_XA;
    float* xn2  = S + O_XN;                        // reuses xn
    float* pbuf = S + O_BIG;                       // reuses qkv1+qkv
    float* cat  = S + O_CAT;
    float* y1   = S + O_BIG;                       // reuses pbuf

    const long sDIM  = (long)DIM * NPIX;
    const long sTRI  = (long)TRI * NPIX;
    const long sHID  = (long)HID * NPIX;
    const long sHID2 = (long)HID2 * NPIX;

    // ---- attention ----
    ln_kernel<<<2048, 256>>>(x, ln1_w, ln1_b, xn);
    bgemm<<<dim3(32, 9, 8), 256>>>(qkv_w, xn, qkv_b, nullptr, qkv1, TRI, DIM, sDIM, sTRI, 0);
    dwconv<<<dim3(16, TRI, 8), 256>>>(qkv1, qkvdw_w, qkvdw_b, qkv, sTRI, sTRI);
    l2n_w<<<24, 256>>>(spf, spfn, 192, 192, 0);                       // spf rows
    l2n_w<<<24576, 256>>>(qkv, qkv, 196608, 24576, sTRI);             // q rows (in place)
    spm_conv<<<dim3(16, 384), 256>>>(spfn, proj_w, proj_b, spm);
    mul_spm<<<dim3(16, 384, 8), 256>>>(qkv, spm);
    l2n_n<<<dim3(768, 8), 256>>>(qkv, sTRI);                          // qs + kr rows
    attn_part<<<dim3(8, 64), 256>>>(qkv, part);
    attn_reduce<<<576, 256>>>(part, temp, attn);
    blend_kernel<<<64, 64>>>(attn, Mb, a1, a2, a3, a4, wmix);
    av_kernel<<<dim3(32, 64), 128>>>(Mb, qkv, oatt);
    bgemm<<<dim3(32, 3, 8), 256>>>(pout_w, oatt, pout_b, x, xa, DIM, DIM, sDIM, sDIM, sDIM);

    // ---- feed forward ----
    ln_kernel<<<2048, 256>>>(xa, ln2_w, ln2_b, xn2);
    bgemm<<<dim3(32, 16, 8), 256>>>(pin_w, xn2, pin_b, nullptr, pbuf, HID2, DIM, sDIM, sHID2, 0);
    dwconv<<<dim3(16, HID, 8), 256>>>(pbuf, dw_w, dw_b, cat, sHID2, sHID2);
    bgemm<<<dim3(32, 8, 8), 256>>>(lin_w, pbuf + (long)HID * NPIX, lin_b, nullptr,
                                   cat + (long)HID * NPIX, HID, HID, sHID2, sHID2, 0);
    bgemm<<<dim3(32, 8, 8), 256>>>(adj_w, cat, adj_b, nullptr, y1, HID, HID2, sHID2, sHID, 0);
    gelu_mul<<<130688, 256>>>(y1, 33456128L);
    bgemm<<<dim3(32, 3, 8), 256>>>(fout_w, y1, fout_b, xa, (float*)d_out, DIM, HID, sHID, sDIM, sDIM);
}

// round 13
// speedup vs baseline: 2.1166x; 1.0012x over previous
#include <cuda_runtime.h>
#include <cstdint>
#include <cmath>

#define NPIX 4096
#define BATCH 8
#define DIM 384
#define TRI 1152
#define NHEADS 8
#define HEADC 48
#define HID 1021
#define HID2 2042

// ---------------- scratch layout (floats), with region reuse ----------------
static const long O_XN   = 0L;                       // 12582912 (xn, later xn2)
static const long O_BIG  = O_XN  + 12582912L;        // 75497472
static const long O_XA   = O_BIG + 75497472L;        // 12582912
static const long O_CAT  = O_XA  + 12582912L;        // 66912256
static const long O_SPFN = O_CAT + 66912256L;        // 12288
static const long O_SPM  = O_SPFN + 12288L;          // 1572864
static const long O_ATTN = O_SPM  + 1572864L;        // 147456
static const long O_M    = O_ATTN + 147456L;         // 147456
static const long O_PART = O_M    + 147456L;         // 1179648
static const long O_END  = O_PART + 1179648L;        // 170635264 floats

__device__ float g_s[170635264L];

// ---------------- LayerNorm over channel dim (per pixel) ----------------
__global__ void ln_kernel(const float* __restrict__ x, const float* __restrict__ w,
                          const float* __restrict__ b, float* __restrict__ y) {
    __shared__ float tile[DIM * 16];
    __shared__ float red[16][16], red2[16][16];
    __shared__ float s_mu[16], s_rs[16];
    int g = blockIdx.x;
    long base = (long)(g >> 8) * DIM * NPIX + (long)(g & 255) * 16;
    int tid = threadIdx.x;
    for (int i = tid; i < DIM * 16; i += 256) {
        int c = i >> 4, p = i & 15;
        tile[i] = x[base + (long)c * NPIX + p];
    }
    __syncthreads();
    {
        int p = tid & 15, chunk = tid >> 4;
        float s = 0.f, s2 = 0.f;
        for (int c = chunk * 24; c < chunk * 24 + 24; c++) {
            float v = tile[c * 16 + p];
            s += v; s2 += v * v;
        }
        red[chunk][p] = s; red2[chunk][p] = s2;
    }
    __syncthreads();
    if (tid < 16) {
        float su = 0.f, su2 = 0.f;
        for (int ch = 0; ch < 16; ch++) { su += red[ch][tid]; su2 += red2[ch][tid]; }
        float mu = su / DIM;
        float var = su2 / DIM - mu * mu;
        s_mu[tid] = mu;
        s_rs[tid] = rsqrtf(var + 1e-5f);
    }
    __syncthreads();
    for (int i = tid; i < DIM * 16; i += 256) {
        int c = i >> 4, p = i & 15;
        y[base + (long)c * NPIX + p] = (tile[i] - s_mu[p]) * s_rs[p] * w[c] + b[c];
    }
}

// ---------------- BF16 tensor-core GEMM: C = A[M,K] * B[K,4096] + bias (+res) ----
// 128x128x32 block tile, 256 threads = 8 warps (4m x 2n), warp tile 32x64.
// Smem holds bf16x2 pairs packed along K: As32[k2][m] = (A[m][2k2], A[m][2k2+1]).
#define P32 136
// cvt.rn.bf16x2.f32 d, a, b  ->  d.hi = bf16(a), d.lo = bf16(b). Pass (hi, lo).
__device__ __forceinline__ uint32_t packbf(float lo, float hi) {
    uint32_t d;
    asm("cvt.rn.bf16x2.f32 %0, %1, %2;" : "=r"(d) : "f"(hi), "f"(lo));
    return d;
}
__device__ __forceinline__ void mma16(float* d, const uint32_t* a, uint32_t b0, uint32_t b1) {
    asm volatile(
        "mma.sync.aligned.m16n8k16.row.col.f32.bf16.bf16.f32 "
        "{%0,%1,%2,%3},{%4,%5,%6,%7},{%8,%9},{%0,%1,%2,%3};"
        : "+f"(d[0]), "+f"(d[1]), "+f"(d[2]), "+f"(d[3])
        : "r"(a[0]), "r"(a[1]), "r"(a[2]), "r"(a[3]), "r"(b0), "r"(b1));
}

__global__ void __launch_bounds__(256) bgemm(
    const float* __restrict__ A, const float* __restrict__ Bm,
    const float* __restrict__ bias, const float* __restrict__ res,
    float* __restrict__ C, int M, int K, long sB, long sC, long sR) {
    __shared__ uint32_t As32[2][16][P32];
    __shared__ uint32_t Bs32[2][16][P32];
    int tid = threadIdx.x;
    int warp = tid >> 5, lane = tid & 31;
    int wm = warp & 3, wn = warp >> 2;
    int t = lane & 3, g = lane >> 2;
    int row0 = blockIdx.y * 128, col0 = blockIdx.x * 128;
    const float* Bb = Bm + (long)blockIdx.z * sB;
    float* Cb = C + (long)blockIdx.z * sC;
    const float* Rb = res ? res + (long)blockIdx.z * sR : nullptr;

    float acc[2][8][4];
#pragma unroll
    for (int mi = 0; mi < 2; mi++)
#pragma unroll
        for (int ni = 0; ni < 8; ni++)
#pragma unroll
            for (int j = 0; j < 4; j++) acc[mi][ni][j] = 0.f;

    // A staging: 2 threads per row; each covers 16 consecutive k (8 pairs)
    int arow = tid & 127;
    int ka2  = (tid >> 7) * 8;          // k2 offset: 0 or 8
    long agrow = (long)(row0 + arow) * K;
    bool arow_ok = (row0 + arow) < M;
    // B staging: thread covers k-pair bk2 (2 rows), 8 cols
    int bk2 = tid >> 4;                  // 0..15
    int bc8 = (tid & 15) * 8;            // 0..120

    float ra[16];
    float4 rb[4];

    int nk = (K + 31) / 32;
    // ---- prologue: stage chunk 0 into buffer 0 ----
    {
        int k0 = 0;
#pragma unroll
        for (int j = 0; j < 16; j++) {
            int kk = k0 + ka2 * 2 + j;
            ra[j] = (arow_ok && kk < K) ? A[agrow + kk] : 0.f;
        }
        int kr0 = k0 + bk2 * 2, kr1 = kr0 + 1;
        rb[0] = rb[1] = rb[2] = rb[3] = make_float4(0.f, 0.f, 0.f, 0.f);
        if (kr0 < K) {
            rb[0] = *(const float4*)&Bb[(long)kr0 * NPIX + col0 + bc8];
            rb[1] = *(const float4*)&Bb[(long)kr0 * NPIX + col0 + bc8 + 4];
        }
        if (kr1 < K) {
            rb[2] = *(const float4*)&Bb[(long)kr1 * NPIX + col0 + bc8];
            rb[3] = *(const float4*)&Bb[(long)kr1 * NPIX + col0 + bc8 + 4];
        }
#pragma unroll
        for (int j = 0; j < 8; j++) As32[0][ka2 + j][arow] = packbf(ra[2 * j], ra[2 * j + 1]);
        Bs32[0][bk2][bc8 + 0] = packbf(rb[0].x, rb[2].x);
        Bs32[0][bk2][bc8 + 1] = packbf(rb[0].y, rb[2].y);
        Bs32[0][bk2][bc8 + 2] = packbf(rb[0].z, rb[2].z);
        Bs32[0][bk2][bc8 + 3] = packbf(rb[0].w, rb[2].w);
        Bs32[0][bk2][bc8 + 4] = packbf(rb[1].x, rb[3].x);
        Bs32[0][bk2][bc8 + 5] = packbf(rb[1].y, rb[3].y);
        Bs32[0][bk2][bc8 + 6] = packbf(rb[1].z, rb[3].z);
        Bs32[0][bk2][bc8 + 7] = packbf(rb[1].w, rb[3].w);
    }
    __syncthreads();

    for (int it = 0; it < nk; it++) {
        int cur = it & 1;
        // prefetch next chunk into registers
        if (it + 1 < nk) {
            int k0 = (it + 1) * 32;
#pragma unroll
            for (int j = 0; j < 16; j++) {
                int kk = k0 + ka2 * 2 + j;
                ra[j] = (arow_ok && kk < K) ? A[agrow + kk] : 0.f;
            }
            int kr0 = k0 + bk2 * 2, kr1 = kr0 + 1;
            rb[0] = rb[1] = rb[2] = rb[3] = make_float4(0.f, 0.f, 0.f, 0.f);
            if (kr0 < K) {
                rb[0] = *(const float4*)&Bb[(long)kr0 * NPIX + col0 + bc8];
                rb[1] = *(const float4*)&Bb[(long)kr0 * NPIX + col0 + bc8 + 4];
            }
            if (kr1 < K) {
                rb[2] = *(const float4*)&Bb[(long)kr1 * NPIX + col0 + bc8];
                rb[3] = *(const float4*)&Bb[(long)kr1 * NPIX + col0 + bc8 + 4];
            }
        }
        // compute on smem[cur]: two k16 sub-chunks
#pragma unroll
        for (int c = 0; c < 2; c++) {
            uint32_t a[2][4];
#pragma unroll
            for (int mi = 0; mi < 2; mi++) {
                int mr = wm * 32 + mi * 16 + g;
                a[mi][0] = As32[cur][c * 8 + t][mr];
                a[mi][1] = As32[cur][c * 8 + t][mr + 8];
                a[mi][2] = As32[cur][c * 8 + t + 4][mr];
                a[mi][3] = As32[cur][c * 8 + t + 4][mr + 8];
            }
#pragma unroll
            for (int ni = 0; ni < 8; ni++) {
                int nc = wn * 64 + ni * 8 + g;
                uint32_t b0 = Bs32[cur][c * 8 + t][nc];
                uint32_t b1 = Bs32[cur][c * 8 + t + 4][nc];
                mma16(acc[0][ni], a[0], b0, b1);
                mma16(acc[1][ni], a[1], b0, b1);
            }
        }
        // store prefetched chunk into other buffer
        if (it + 1 < nk) {
            int nxt = 1 - cur;
#pragma unroll
            for (int j = 0; j < 8; j++) As32[nxt][ka2 + j][arow] = packbf(ra[2 * j], ra[2 * j + 1]);
            Bs32[nxt][bk2][bc8 + 0] = packbf(rb[0].x, rb[2].x);
            Bs32[nxt][bk2][bc8 + 1] = packbf(rb[0].y, rb[2].y);
            Bs32[nxt][bk2][bc8 + 2] = packbf(rb[0].z, rb[2].z);
            Bs32[nxt][bk2][bc8 + 3] = packbf(rb[0].w, rb[2].w);
            Bs32[nxt][bk2][bc8 + 4] = packbf(rb[1].x, rb[3].x);
            Bs32[nxt][bk2][bc8 + 5] = packbf(rb[1].y, rb[3].y);
            Bs32[nxt][bk2][bc8 + 6] = packbf(rb[1].z, rb[3].z);
            Bs32[nxt][bk2][bc8 + 7] = packbf(rb[1].w, rb[3].w);
        }
        __syncthreads();
    }

    // epilogue: bias + optional residual, float2 stores
#pragma unroll
    for (int mi = 0; mi < 2; mi++) {
        int r0r = row0 + wm * 32 + mi * 16 + g;
        int r1r = r0r + 8;
        float bs0 = (r0r < M) ? bias[r0r] : 0.f;
        float bs1 = (r1r < M) ? bias[r1r] : 0.f;
#pragma unroll
        for (int ni = 0; ni < 8; ni++) {
            int c = col0 + wn * 64 + ni * 8 + 2 * t;
            if (r0r < M) {
                long off = (long)r0r * NPIX + c;
                float2 v = make_float2(acc[mi][ni][0] + bs0, acc[mi][ni][1] + bs0);
                if (Rb) { v.x += Rb[off]; v.y += Rb[off + 1]; }
                *(float2*)&Cb[off] = v;
            }
            if (r1r < M) {
                long off = (long)r1r * NPIX + c;
                float2 v = make_float2(acc[mi][ni][2] + bs1, acc[mi][ni][3] + bs1);
                if (Rb) { v.x += Rb[off]; v.y += Rb[off + 1]; }
                *(float2*)&Cb[off] = v;
            }
        }
    }
}

// ---------------- depthwise 3x3 conv, pad 1 ----------------
__global__ void dwconv(const float* __restrict__ x, const float* __restrict__ w,
                       const float* __restrict__ bias, float* __restrict__ y,
                       long sIn, long sOut) {
    int p = blockIdx.x * 256 + threadIdx.x;
    int c = blockIdx.y, b = blockIdx.z;
    int h = p >> 6, wc = p & 63;
    const float* xin = x + (long)b * sIn + (long)c * NPIX;
    float acc = bias[c];
    const float* wt = w + c * 9;
#pragma unroll
    for (int dh = -1; dh <= 1; dh++) {
        int hh = h + dh;
        if (hh < 0 || hh >= 64) continue;
#pragma unroll
        for (int dw = -1; dw <= 1; dw++) {
            int ww = wc + dw;
            if (ww < 0 || ww >= 64) continue;
            acc += xin[hh * 64 + ww] * wt[(dh + 1) * 3 + (dw + 1)];
        }
    }
    y[(long)b * sOut + (long)c * NPIX + p] = acc;
}

// ---------------- L2 normalize over W (rows of 64), warp per row ------------
__global__ void l2n_w(const float* __restrict__ src, float* __restrict__ dst,
                      long nrows, long rows_per_b, long sB) {
    long row = (long)blockIdx.x * 8 + (threadIdx.x >> 5);
    if (row >= nrows) return;
    int lane = threadIdx.x & 31;
    long b = row / rows_per_b;
    long off = b * sB + (row % rows_per_b) * 64;
    float v0 = src[off + lane], v1 = src[off + lane + 32];
    float s = v0 * v0 + v1 * v1;
#pragma unroll
    for (int o = 16; o; o >>= 1) s += __shfl_xor_sync(0xffffffffu, s, o);
    float inv = 1.f / fmaxf(sqrtf(s), 1e-12f);
    dst[off + lane] = v0 * inv;
    dst[off + lane + 32] = v1 * inv;
}

// ---------------- L2 normalize over 4096 (in place), block per row ----------
__global__ void l2n_n(float* __restrict__ x, long sB) {
    float* r = x + (long)blockIdx.y * sB + (long)blockIdx.x * NPIX;
    __shared__ float red[8];
    int tid = threadIdx.x;
    float s = 0.f;
    for (int i = tid; i < NPIX; i += 256) { float v = r[i]; s += v * v; }
#pragma unroll
    for (int o = 16; o; o >>= 1) s += __shfl_xor_sync(0xffffffffu, s, o);
    if ((tid & 31) == 0) red[tid >> 5] = s;
    __syncthreads();
    if (tid == 0) {
        float tsum = 0.f;
        for (int i = 0; i < 8; i++) tsum += red[i];
        red[0] = 1.f / fmaxf(sqrtf(tsum), 1e-12f);
    }
    __syncthreads();
    float inv = red[0];
    for (int i = tid; i < NPIX; i += 256) r[i] *= inv;
}

// ---------------- spm = conv3x3(spfn broadcast, proj_w) + proj_b -------------
__global__ void spm_conv(const float* __restrict__ spfn, const float* __restrict__ w,
                         const float* __restrict__ b, float* __restrict__ spm) {
    int p = blockIdx.x * 256 + threadIdx.x;
    int o = blockIdx.y;
    int h = p >> 6, wc = p & 63;
    float acc = b[o];
    for (int c = 0; c < 3; c++) {
#pragma unroll
        for (int dh = -1; dh <= 1; dh++) {
            int hh = h + dh;
            if (hh < 0 || hh >= 64) continue;
#pragma unroll
            for (int dw = -1; dw <= 1; dw++) {
                int ww = wc + dw;
                if (ww < 0 || ww >= 64) continue;
                acc += spfn[c * NPIX + hh * 64 + ww] * w[o * 27 + c * 9 + (dh + 1) * 3 + (dw + 1)];
            }
        }
    }
    spm[(long)o * NPIX + p] = acc;
}

// ---------------- q *= spm (broadcast over batch) ----------------
__global__ void mul_spm(float* __restrict__ q, const float* __restrict__ spm) {
    int p = blockIdx.x * 256 + threadIdx.x;
    int c = blockIdx.y, b = blockIdx.z;
    q[(long)b * TRI * NPIX + (long)c * NPIX + p] *= spm[(long)c * NPIX + p];
}

// ---------------- attn partial: qs @ kr^T over 512-pixel slice -------------
__global__ void attn_part(const float* __restrict__ qkv, float* __restrict__ part) {
    int s = blockIdx.x, bh = blockIdx.y;
    int b = bh >> 3, hd = bh & 7;
    const float* Q  = qkv + (long)b * TRI * NPIX + (long)(hd * HEADC) * NPIX;
    const float* Kp = qkv + (long)b * TRI * NPIX + (long)(DIM + hd * HEADC) * NPIX;
    __shared__ float Qs[48][65], Ks[48][65];
    int tid = threadIdx.x;
    int ti = tid >> 4, tj = tid & 15;
    float acc[3][3] = {};
    for (int p0 = s * 512; p0 < s * 512 + 512; p0 += 64) {
        for (int i = tid; i < 48 * 64; i += 256) {
            int r = i >> 6, c = i & 63;
            Qs[r][c] = Q[(long)r * NPIX + p0 + c];
            Ks[r][c] = Kp[(long)r * NPIX + p0 + c];
        }
        __syncthreads();
#pragma unroll 4
        for (int p = 0; p < 64; p++) {
            float qr[3], kk[3];
#pragma unroll
            for (int r = 0; r < 3; r++) { qr[r] = Qs[ti * 3 + r][p]; kk[r] = Ks[tj * 3 + r][p]; }
#pragma unroll
            for (int r = 0; r < 3; r++)
#pragma unroll
                for (int c = 0; c < 3; c++) acc[r][c] += qr[r] * kk[c];
        }
        __syncthreads();
    }
    float* P = part + ((long)s * 64 + bh) * 2304;
#pragma unroll
    for (int r = 0; r < 3; r++)
#pragma unroll
        for (int c = 0; c < 3; c++)
            P[(ti * 3 + r) * 48 + tj * 3 + c] = acc[r][c];
}

// ---------------- reduce partials + temperature ----------------
__global__ void attn_reduce(const float* __restrict__ part, const float* __restrict__ temp,
                            float* __restrict__ attn) {
    int idx = blockIdx.x * 256 + threadIdx.x;  // < 147456
    int bh = idx / 2304;
    int hd = bh & 7;
    float s = 0.f;
#pragma unroll
    for (int sl = 0; sl < 8; sl++) s += part[(long)sl * 147456 + idx];
    attn[idx] = s * temp[hd];
}

// ---------------- blend: relu + 4x topk masked softmax folded into one M ----
__global__ void blend_kernel(const float* __restrict__ attn, float* __restrict__ Mout,
                             const float* __restrict__ a1, const float* __restrict__ a2,
                             const float* __restrict__ a3, const float* __restrict__ a4,
                             const float* __restrict__ wmix) {
    int bh = blockIdx.x;
    int i = threadIdx.x;
    if (i >= 48) return;
    const float* row = attn + (long)bh * 2304 + i * 48;
    float arr[48], srt[48];
    for (int j = 0; j < 48; j++) { arr[j] = row[j]; srt[j] = arr[j]; }
    for (int a = 1; a < 48; a++) {
        float key = srt[a];
        int b2 = a - 1;
        while (b2 >= 0 && srt[b2] < key) { srt[b2 + 1] = srt[b2]; b2--; }
        srt[b2 + 1] = key;
    }
    float A[4] = {a1[0], a2[0], a3[0], a4[0]};
    float w0 = wmix[0], w1 = wmix[1];
    float mw = fmaxf(w0, w1);
    float e0 = expf(w0 - mw), e1 = expf(w1 - mw);
    float wsm0 = e0 / (e0 + e1), wsm1 = e1 / (e0 + e1);
    float csum = A[0] + A[1] + A[2] + A[3];
    float outr[48];
    for (int j = 0; j < 48; j++) outr[j] = wsm0 * csum * fmaxf(arr[j], 0.f);
    const int kks[4] = {24, 32, 36, 38};
    for (int tt = 0; tt < 4; tt++) {
        float thr = srt[kks[tt] - 1];
        float mv[48];
        float mx = -1e30f;
        for (int j = 0; j < 48; j++) {
            float m = (arr[j] >= thr) ? arr[j] : arr[j] * 1e-6f;
            mv[j] = m;
            mx = fmaxf(mx, m);
        }
        float Z = 0.f;
        for (int j = 0; j < 48; j++) { mv[j] = expf(mv[j] - mx); Z += mv[j]; }
        float sc = wsm1 * A[tt] / Z;
        for (int j = 0; j < 48; j++) outr[j] += sc * mv[j];
    }
    float* o = Mout + (long)bh * 2304 + i * 48;
    for (int j = 0; j < 48; j++) o[j] = outr[j];
}

// ---------------- out = M(48x48) @ V(48x4096) ----------------
__global__ void av_kernel(const float* __restrict__ Mb, const float* __restrict__ qkv,
                          float* __restrict__ out) {
    int bh = blockIdx.y;
    int b = bh >> 3, hd = bh & 7;
    const float* V = qkv + (long)b * TRI * NPIX + (long)(2 * DIM + hd * HEADC) * NPIX;
    __shared__ float Ms[48][49];
    int tid = threadIdx.x;
    for (int i = tid; i < 2304; i += 128) Ms[i / 48][i % 48] = Mb[(long)bh * 2304 + i];
    __syncthreads();
    int p = blockIdx.x * 128 + tid;
    float vreg[48];
#pragma unroll
    for (int j = 0; j < 48; j++) vreg[j] = V[(long)j * NPIX + p];
    float* O = out + (long)b * DIM * NPIX + (long)(hd * HEADC) * NPIX;
#pragma unroll 4
    for (int i = 0; i < 48; i++) {
        float s = 0.f;
#pragma unroll
        for (int j = 0; j < 48; j++) s += Ms[i][j] * vreg[j];
        O[(long)i * NPIX + p] = s;
    }
}

// ---------------- f = gelu(y) * y (exact gelu), in place ----------------
__global__ void gelu_mul(float* __restrict__ y, long n) {
    long i = (long)blockIdx.x * 256 + threadIdx.x;
    if (i >= n) return;
    float v = y[i];
    float g = 0.5f * v * (1.f + erff(v * 0.70710678118654752f));
    y[i] = g * v;
}

// ================================================================
extern "C" void kernel_launch(void* const* d_in, const int* in_sizes, int n_in,
                              void* d_out, int out_size) {
    const float* x       = (const float*)d_in[0];
    const float* spf     = (const float*)d_in[1];
    const float* ln1_w   = (const float*)d_in[2];
    const float* ln1_b   = (const float*)d_in[3];
    const float* qkv_w   = (const float*)d_in[4];
    const float* qkv_b   = (const float*)d_in[5];
    const float* qkvdw_w = (const float*)d_in[6];
    const float* qkvdw_b = (const float*)d_in[7];
    const float* proj_w  = (const float*)d_in[8];
    const float* proj_b  = (const float*)d_in[9];
    const float* temp    = (const float*)d_in[10];
    const float* a1      = (const float*)d_in[11];
    const float* a2      = (const float*)d_in[12];
    const float* a3      = (const float*)d_in[13];
    const float* a4      = (const float*)d_in[14];
    const float* wmix    = (const float*)d_in[15];
    const float* pout_w  = (const float*)d_in[16];
    const float* pout_b  = (const float*)d_in[17];
    const float* ln2_w   = (const float*)d_in[18];
    const float* ln2_b   = (const float*)d_in[19];
    const float* pin_w   = (const float*)d_in[20];
    const float* pin_b   = (const float*)d_in[21];
    const float* dw_w    = (const float*)d_in[22];
    const float* dw_b    = (const float*)d_in[23];
    const float* lin_w   = (const float*)d_in[24];
    const float* lin_b   = (const float*)d_in[25];
    const float* adj_w   = (const float*)d_in[26];
    const float* adj_b   = (const float*)d_in[27];
    const float* fout_w  = (const float*)d_in[28];
    const float* fout_b  = (const float*)d_in[29];

    float* S = nullptr;
    cudaGetSymbolAddress((void**)&S, g_s);
    float* xn   = S + O_XN;
    float* qkv1 = S + O_BIG;
    float* qkv  = S + O_BIG + 37748736L;
    float* spfn = S + O_SPFN;
    float* spm  = S + O_SPM;
    float* attn = S + O_ATTN;
    float* Mb   = S + O_M;
    float* part = S + O_PART;
    float* oatt = S + O_BIG;                       // reuses qkv1
    float* xa   = S + O_XA;
    float* xn2  = S + O_XN;                        // reuses xn
    float* pbuf = S + O_BIG;                       // reuses qkv1+qkv
    float* cat  = S + O_CAT;
    float* y1   = S + O_BIG;                       // reuses pbuf

    const long sDIM  = (long)DIM * NPIX;
    const long sTRI  = (long)TRI * NPIX;
    const long sHID  = (long)HID * NPIX;
    const long sHID2 = (long)HID2 * NPIX;

    // ---- attention ----
    ln_kernel<<<2048, 256>>>(x, ln1_w, ln1_b, xn);
    bgemm<<<dim3(32, 9, 8), 256>>>(qkv_w, xn, qkv_b, nullptr, qkv1, TRI, DIM, sDIM, sTRI, 0);
    dwconv<<<dim3(16, TRI, 8), 256>>>(qkv1, qkvdw_w, qkvdw_b, qkv, sTRI, sTRI);
    l2n_w<<<24, 256>>>(spf, spfn, 192, 192, 0);                       // spf rows
    l2n_w<<<24576, 256>>>(qkv, qkv, 196608, 24576, sTRI);             // q rows (in place)
    spm_conv<<<dim3(16, 384), 256>>>(spfn, proj_w, proj_b, spm);
    mul_spm<<<dim3(16, 384, 8), 256>>>(qkv, spm);
    l2n_n<<<dim3(768, 8), 256>>>(qkv, sTRI);                          // qs + kr rows
    attn_part<<<dim3(8, 64), 256>>>(qkv, part);
    attn_reduce<<<576, 256>>>(part, temp, attn);
    blend_kernel<<<64, 64>>>(attn, Mb, a1, a2, a3, a4, wmix);
    av_kernel<<<dim3(32, 64), 128>>>(Mb, qkv, oatt);
    bgemm<<<dim3(32, 3, 8), 256>>>(pout_w, oatt, pout_b, x, xa, DIM, DIM, sDIM, sDIM, sDIM);

    // ---- feed forward ----
    ln_kernel<<<2048, 256>>>(xa, ln2_w, ln2_b, xn2);
    bgemm<<<dim3(32, 16, 8), 256>>>(pin_w, xn2, pin_b, nullptr, pbuf, HID2, DIM, sDIM, sHID2, 0);
    dwconv<<<dim3(16, HID, 8), 256>>>(pbuf, dw_w, dw_b, cat, sHID2, sHID2);
    bgemm<<<dim3(32, 8, 8), 256>>>(lin_w, pbuf + (long)HID * NPIX, lin_b, nullptr,
                                   cat + (long)HID * NPIX, HID, HID, sHID2, sHID2, 0);
    bgemm<<<dim3(32, 8, 8), 256>>>(adj_w, cat, adj_b, nullptr, y1, HID, HID2, sHID2, sHID, 0);
    gelu_mul<<<130688, 256>>>(y1, 33456128L);
    bgemm<<<dim3(32, 3, 8), 256>>>(fout_w, y1, fout_b, xa, (float*)d_out, DIM, HID, sHID, sDIM, sDIM);
}